// round 11
// baseline (speedup 1.0000x reference)
#include <cuda_runtime.h>
#include <cuda_bf16.h>
#include <cstdint>

// ---------------------------------------------------------------------------
// AxialAttention (K=56, G=8, CIN=512, COUT=512)
//   k0 : transpose+split W -> g_whi/g_wlo [1024 n][512 k] bf16
//   k1 : qkv GEMM via mma.sync m16n8k16 bf16 (3-product split), inline x split,
//        BN fold, writes Q/K/V transposed to [b][w][row][c] fp32
//   k2 : logits via mma.sync: QK^T + diag-gather of Q*qrel^T and K*krel^T
//   k3 : in-place softmax over w
//   k4 : attn_out via mma.sync: sv = sim*V, sve = S'*vrel (banded->dense), BN
// ---------------------------------------------------------------------------

#define EPS 1e-3f

__device__ float g_Q[12845056];   // [16][56 w][56 i][256]
__device__ float g_K[12845056];
__device__ float g_V[25690112];   // [16][56 w][56 j][512]
__device__ float g_L[22478848];   // [16][56 w][8 g][3136 ij]
__device__ __align__(16) __nv_bfloat16 g_whi[524288];    // [1024 n][512 k]
__device__ __align__(16) __nv_bfloat16 g_wlo[524288];

__device__ __forceinline__ uint32_t smem_u32(const void* p) {
    uint32_t a;
    asm("{ .reg .u64 t; cvta.to.shared.u64 t, %1; cvt.u32.u64 %0, t; }" : "=r"(a) : "l"(p));
    return a;
}
__device__ __forceinline__ void ldsm4(unsigned* r, uint32_t a) {
    asm volatile("ldmatrix.sync.aligned.m8n8.x4.shared.b16 {%0,%1,%2,%3}, [%4];"
        : "=r"(r[0]), "=r"(r[1]), "=r"(r[2]), "=r"(r[3]) : "r"(a));
}
__device__ __forceinline__ void mma16816(float* d, const unsigned* a, const unsigned* b) {
    asm volatile("mma.sync.aligned.m16n8k16.row.col.f32.bf16.bf16.f32 "
        "{%0,%1,%2,%3}, {%4,%5,%6,%7}, {%8,%9}, {%0,%1,%2,%3};"
        : "+f"(d[0]), "+f"(d[1]), "+f"(d[2]), "+f"(d[3])
        : "r"(a[0]), "r"(a[1]), "r"(a[2]), "r"(a[3]), "r"(b[0]), "r"(b[1]));
}
// smem swizzle: rows of 32 bf16 (64B = 4 chunks of 16B)
__device__ __forceinline__ uint32_t swz(int row, int chunk) {
    return (uint32_t)(row * 64 + ((chunk ^ (row & 3) ^ ((row >> 2) & 1)) << 4));
}
// smem swizzle: rows of 64 bf16 (128B = 8 chunks of 16B)
__device__ __forceinline__ uint32_t swz128(int row, int chunk) {
    return (uint32_t)(row * 128 + ((chunk ^ (row & 7)) << 4));
}
__device__ __forceinline__ void split_pair(float a, float b, unsigned& hi2, unsigned& lo2) {
    __nv_bfloat162 h = __floats2bfloat162_rn(a, b);
    float ra = a - __bfloat162float(h.x);
    float rb = b - __bfloat162float(h.y);
    __nv_bfloat162 l = __floats2bfloat162_rn(ra, rb);
    hi2 = *(unsigned*)&h;
    lo2 = *(unsigned*)&l;
}
__device__ __forceinline__ void split8(float4 a, float4 b, uint4& hi, uint4& lo) {
    split_pair(a.x, a.y, hi.x, lo.x);
    split_pair(a.z, a.w, hi.y, lo.y);
    split_pair(b.x, b.y, hi.z, lo.z);
    split_pair(b.z, b.w, hi.w, lo.w);
}
__device__ __forceinline__ void split1(float v, __nv_bfloat16& h, __nv_bfloat16& l) {
    h = __float2bfloat16_rn(v);
    l = __float2bfloat16_rn(v - __bfloat162float(h));
}

// ---------------------------------------------------------------------------
// k0: transpose + split W -> g_whi/g_wlo [n][k]
// ---------------------------------------------------------------------------
__global__ __launch_bounds__(256) void split_w_kernel(
    const float* __restrict__ Wq, const float* __restrict__ Wk, const float* __restrict__ Wv)
{
    __shared__ float t[32][33];
    const int n0 = blockIdx.x * 32, k0 = blockIdx.y * 32;
    const float* W; int ncols, col0;
    if (n0 < 256)      { W = Wq; ncols = 256; col0 = n0;       }
    else if (n0 < 512) { W = Wk; ncols = 256; col0 = n0 - 256; }
    else               { W = Wv; ncols = 512; col0 = n0 - 512; }
    const int tx = threadIdx.x & 31, ty = threadIdx.x >> 5;
    #pragma unroll
    for (int i = 0; i < 32; i += 8)
        t[ty + i][tx] = W[(k0 + ty + i) * ncols + col0 + tx];
    __syncthreads();
    #pragma unroll
    for (int i = 0; i < 32; i += 8) {
        const float v = t[tx][ty + i];
        const __nv_bfloat16 h = __float2bfloat16_rn(v);
        g_whi[(n0 + ty + i) * 512 + k0 + tx] = h;
        g_wlo[(n0 + ty + i) * 512 + k0 + tx] = __float2bfloat16_rn(v - __bfloat162float(h));
    }
}

// ---------------------------------------------------------------------------
// k1: mma.sync bf16 QKV GEMM. BM=128 BN=128 BK=32, 256 thr (8 warps, 4Mx2N)
// ---------------------------------------------------------------------------
#define STG 32768
#define SMEM_MMA (2*STG + 1024)

__global__ __launch_bounds__(256, 1) void qkv_mma_kernel(
    const float* __restrict__ x,
    const float* __restrict__ pq, const float* __restrict__ pk, const float* __restrict__ pv)
{
    extern __shared__ char smem[];
    float* Ssc = (float*)(smem + 2*STG);
    float* Tsc = Ssc + 128;

    const int tid  = threadIdx.x;
    const int lane = tid & 31, wid = tid >> 5;
    const int mbase = (wid >> 1) * 32;
    const int nbase = (wid & 1) * 64;
    const int n0 = blockIdx.x * 128;
    const int m0 = blockIdx.y * 128;
    const uint32_t sb = smem_u32(smem);

    const float* P; float* dst; int ncols, colbase;
    if (n0 < 256)      { P = pq; dst = g_Q; ncols = 256; colbase = n0;       }
    else if (n0 < 512) { P = pk; dst = g_K; ncols = 256; colbase = n0 - 256; }
    else               { P = pv; dst = g_V; ncols = 512; colbase = n0 - 512; }

    if (tid < 128) {
        const int ch = colbase + tid;
        const float s = P[ch] * rsqrtf(P[3*ncols + ch] + EPS);
        Ssc[tid] = s;
        Tsc[tid] = P[ncols + ch] - P[2*ncols + ch] * s;
    }

    const int prow = tid >> 1;
    const int pc   = (tid & 1) * 2;
    const size_t aoff = (size_t)(m0 + prow) * 512;
    const size_t boff = (size_t)(n0 + prow) * 512;
    const uint32_t so0 = swz(prow, pc), so1 = swz(prow, pc + 1);

    float acc[2][8][4];
    #pragma unroll
    for (int mt = 0; mt < 2; mt++)
        #pragma unroll
        for (int nt = 0; nt < 8; nt++)
            #pragma unroll
            for (int c = 0; c < 4; c++) acc[mt][nt][c] = 0.f;

    // prologue: stage 0
    {
        const int koff = pc * 8;
        const float4* px = (const float4*)(x + aoff + koff);
        float4 x0 = px[0], x1 = px[1], x2 = px[2], x3 = px[3];
        uint4 h0, l0, h1, l1;
        split8(x0, x1, h0, l0);
        split8(x2, x3, h1, l1);
        const uint4* pwh = (const uint4*)(g_whi + boff + koff);
        const uint4* pwl = (const uint4*)(g_wlo + boff + koff);
        char* s = smem;
        *(uint4*)(s + so0)          = h0; *(uint4*)(s + so1)          = h1;
        *(uint4*)(s + 8192  + so0)  = l0; *(uint4*)(s + 8192  + so1)  = l1;
        *(uint4*)(s + 16384 + so0)  = pwh[0]; *(uint4*)(s + 16384 + so1) = pwh[1];
        *(uint4*)(s + 24576 + so0)  = pwl[0]; *(uint4*)(s + 24576 + so1) = pwl[1];
    }
    __syncthreads();

    for (int ks = 0; ks < 16; ks++) {
        const int cur = ks & 1;
        float4 fx[4]; uint4 fw[4];
        if (ks < 15) {
            const int koff = (ks + 1) * 32 + pc * 8;
            const float4* px = (const float4*)(x + aoff + koff);
            fx[0] = px[0]; fx[1] = px[1]; fx[2] = px[2]; fx[3] = px[3];
            const uint4* pwh = (const uint4*)(g_whi + boff + koff);
            const uint4* pwl = (const uint4*)(g_wlo + boff + koff);
            fw[0] = pwh[0]; fw[1] = pwh[1];
            fw[2] = pwl[0]; fw[3] = pwl[1];
        }
        const uint32_t stb = sb + cur * STG;
        #pragma unroll
        for (int kst = 0; kst < 2; kst++) {
            unsigned ah[2][4], al[2][4], bh[16], bl[16];
            #pragma unroll
            for (int mt = 0; mt < 2; mt++) {
                const int row = mbase + mt*16 + (lane & 15);
                const int ch  = kst*2 + (lane >> 4);
                const uint32_t ad = stb + swz(row, ch);
                ldsm4(ah[mt], ad);
                ldsm4(al[mt], ad + 8192);
            }
            #pragma unroll
            for (int p = 0; p < 4; p++) {
                const int row = nbase + (2*p + (lane >> 4)) * 8 + (lane & 7);
                const int ch  = kst*2 + ((lane >> 3) & 1);
                const uint32_t bd = stb + 16384 + swz(row, ch);
                ldsm4(&bh[p*4], bd);
                ldsm4(&bl[p*4], bd + 8192);
            }
            #pragma unroll
            for (int mt = 0; mt < 2; mt++)
                #pragma unroll
                for (int nt = 0; nt < 8; nt++) {
                    mma16816(acc[mt][nt], ah[mt], &bh[nt*2]);
                    mma16816(acc[mt][nt], al[mt], &bh[nt*2]);
                    mma16816(acc[mt][nt], ah[mt], &bl[nt*2]);
                }
        }
        __syncthreads();
        if (ks < 15) {
            uint4 h0, l0, h1, l1;
            split8(fx[0], fx[1], h0, l0);
            split8(fx[2], fx[3], h1, l1);
            char* s = smem + (cur ^ 1) * STG;
            *(uint4*)(s + so0)         = h0;    *(uint4*)(s + so1)         = h1;
            *(uint4*)(s + 8192  + so0) = l0;    *(uint4*)(s + 8192  + so1) = l1;
            *(uint4*)(s + 16384 + so0) = fw[0]; *(uint4*)(s + 16384 + so1) = fw[1];
            *(uint4*)(s + 24576 + so0) = fw[2]; *(uint4*)(s + 24576 + so1) = fw[3];
            __syncthreads();
        }
    }

    // epilogue: BN fold, transposed store [b][w][row][c]
    #pragma unroll
    for (int mt = 0; mt < 2; mt++) {
        #pragma unroll
        for (int half = 0; half < 2; half++) {
            const int m = m0 + mbase + mt*16 + (lane >> 2) + half*8;
            const int b = m / 3136;
            const int rem = m - b*3136;
            const int i = rem / 56;
            const int w = rem - i*56;
            float* dr = dst + (size_t)((b*56 + w)*56 + i) * ncols + colbase;
            #pragma unroll
            for (int nt = 0; nt < 8; nt++) {
                const int col = nbase + nt*8 + (lane & 3)*2;
                float2 o;
                o.x = acc[mt][nt][half*2+0] * Ssc[col]   + Tsc[col];
                o.y = acc[mt][nt][half*2+1] * Ssc[col+1] + Tsc[col+1];
                *(float2*)(dr + col) = o;
            }
        }
    }
}

// ---------------------------------------------------------------------------
// k2: logits via mma.sync. One block per (b,w,g), 128 threads (4 warps).
// ---------------------------------------------------------------------------
#define OFF_QHI  0
#define OFF_QLO  4096
#define OFF_KHI  8192
#define OFF_KLO  12288
#define OFF_RQHI 16384
#define OFF_RQLO 23552
#define OFF_RKHI 30720
#define OFF_RKLO 37888
#define OFF_QRS  45056
#define OFF_KRS  74240
#define SMEM_LOGITS 103424

__global__ __launch_bounds__(128) void logits_mma_kernel(
    const float* __restrict__ q_rel, const float* __restrict__ k_rel,
    const float* __restrict__ pqk, const float* __restrict__ pqr, const float* __restrict__ pkr)
{
    extern __shared__ char sm[];
    const uint32_t sb = smem_u32(sm);
    const int tid = threadIdx.x;
    const int lane = tid & 31, wid = tid >> 5;
    const int bw = blockIdx.x;
    const int g  = blockIdx.y;

    const float* qbase = g_Q + (size_t)bw * 56 * 256 + g * 32;
    const float* kbase = g_K + (size_t)bw * 56 * 256 + g * 32;
    for (int t = tid; t < 224; t += 128) {
        const int row = t >> 2, ch = t & 3;
        const uint32_t o = swz(row, ch);
        float4 a = *(const float4*)(qbase + row*256 + ch*8);
        float4 b = *(const float4*)(qbase + row*256 + ch*8 + 4);
        uint4 hi, lo; split8(a, b, hi, lo);
        *(uint4*)(sm + OFF_QHI + o) = hi;
        *(uint4*)(sm + OFF_QLO + o) = lo;
        a = *(const float4*)(kbase + row*256 + ch*8);
        b = *(const float4*)(kbase + row*256 + ch*8 + 4);
        split8(a, b, hi, lo);
        *(uint4*)(sm + OFF_KHI + o) = hi;
        *(uint4*)(sm + OFF_KLO + o) = lo;
    }
    for (int t = tid; t < 444; t += 128) {
        const int row = t >> 2, ch = t & 3;
        const uint32_t o = swz(row, ch);
        float4 a = *(const float4*)(q_rel + row*32 + ch*8);
        float4 b = *(const float4*)(q_rel + row*32 + ch*8 + 4);
        uint4 hi, lo; split8(a, b, hi, lo);
        *(uint4*)(sm + OFF_RQHI + o) = hi;
        *(uint4*)(sm + OFF_RQLO + o) = lo;
        a = *(const float4*)(k_rel + row*32 + ch*8);
        b = *(const float4*)(k_rel + row*32 + ch*8 + 4);
        split8(a, b, hi, lo);
        *(uint4*)(sm + OFF_RKHI + o) = hi;
        *(uint4*)(sm + OFF_RKLO + o) = lo;
    }
    __syncthreads();

    const float sqk = pqk[g] * rsqrtf(pqk[24+g] + EPS);
    const float sqr = pqr[g] * rsqrtf(pqr[24+g] + EPS);
    const float skr = pkr[g] * rsqrtf(pkr[24+g] + EPS);
    const float tsum = (pqk[8+g] - pqk[16+g]*sqk)
                     + (pqr[8+g] - pqr[16+g]*sqr)
                     + (pkr[8+g] - pkr[16+g]*skr);

    const int mrow0 = wid * 16;
    float* qrs = (float*)(sm + OFF_QRS);
    float* krs = (float*)(sm + OFF_KRS);
    const int fr = lane >> 2, fc = (lane & 3) * 2;

    // --- Qr_full = Q * qrel^T
    {
        unsigned ah[2][4], al[2][4];
        #pragma unroll
        for (int kst = 0; kst < 2; kst++) {
            const int row = mrow0 + (lane & 15);
            const int ch  = kst*2 + (lane >> 4);
            ldsm4(ah[kst], sb + OFF_QHI + swz(row, ch));
            ldsm4(al[kst], sb + OFF_QLO + swz(row, ch));
        }
        float acc[14][4];
        #pragma unroll
        for (int nt = 0; nt < 14; nt++)
            #pragma unroll
            for (int c = 0; c < 4; c++) acc[nt][c] = 0.f;
        #pragma unroll
        for (int kst = 0; kst < 2; kst++)
            #pragma unroll
            for (int p = 0; p < 7; p++) {
                unsigned bh[4], bl[4];
                const int brow = (2*p + (lane >> 4)) * 8 + (lane & 7);
                const int bch  = kst*2 + ((lane >> 3) & 1);
                ldsm4(bh, sb + OFF_RQHI + swz(brow, bch));
                ldsm4(bl, sb + OFF_RQLO + swz(brow, bch));
                #pragma unroll
                for (int t2 = 0; t2 < 2; t2++) {
                    mma16816(acc[2*p+t2], ah[kst], &bh[2*t2]);
                    mma16816(acc[2*p+t2], al[kst], &bh[2*t2]);
                    mma16816(acc[2*p+t2], ah[kst], &bl[2*t2]);
                }
            }
        #pragma unroll
        for (int nt = 0; nt < 14; nt++) {
            *(float2*)&qrs[(mrow0+fr)*114   + nt*8 + fc] = make_float2(acc[nt][0], acc[nt][1]);
            *(float2*)&qrs[(mrow0+fr+8)*114 + nt*8 + fc] = make_float2(acc[nt][2], acc[nt][3]);
        }
    }
    // --- Kr_full = K * krel^T
    {
        unsigned ah[2][4], al[2][4];
        #pragma unroll
        for (int kst = 0; kst < 2; kst++) {
            const int row = mrow0 + (lane & 15);
            const int ch  = kst*2 + (lane >> 4);
            ldsm4(ah[kst], sb + OFF_KHI + swz(row, ch));
            ldsm4(al[kst], sb + OFF_KLO + swz(row, ch));
        }
        float acc[14][4];
        #pragma unroll
        for (int nt = 0; nt < 14; nt++)
            #pragma unroll
            for (int c = 0; c < 4; c++) acc[nt][c] = 0.f;
        #pragma unroll
        for (int kst = 0; kst < 2; kst++)
            #pragma unroll
            for (int p = 0; p < 7; p++) {
                unsigned bh[4], bl[4];
                const int brow = (2*p + (lane >> 4)) * 8 + (lane & 7);
                const int bch  = kst*2 + ((lane >> 3) & 1);
                ldsm4(bh, sb + OFF_RKHI + swz(brow, bch));
                ldsm4(bl, sb + OFF_RKLO + swz(brow, bch));
                #pragma unroll
                for (int t2 = 0; t2 < 2; t2++) {
                    mma16816(acc[2*p+t2], ah[kst], &bh[2*t2]);
                    mma16816(acc[2*p+t2], al[kst], &bh[2*t2]);
                    mma16816(acc[2*p+t2], ah[kst], &bl[2*t2]);
                }
            }
        #pragma unroll
        for (int nt = 0; nt < 14; nt++) {
            *(float2*)&krs[(mrow0+fr)*114   + nt*8 + fc] = make_float2(acc[nt][0], acc[nt][1]);
            *(float2*)&krs[(mrow0+fr+8)*114 + nt*8 + fc] = make_float2(acc[nt][2], acc[nt][3]);
        }
    }
    // --- QK = Q * K^T
    float qk[8][4];
    #pragma unroll
    for (int nt = 0; nt < 8; nt++)
        #pragma unroll
        for (int c = 0; c < 4; c++) qk[nt][c] = 0.f;
    {
        unsigned ah[2][4], al[2][4];
        #pragma unroll
        for (int kst = 0; kst < 2; kst++) {
            const int row = mrow0 + (lane & 15);
            const int ch  = kst*2 + (lane >> 4);
            ldsm4(ah[kst], sb + OFF_QHI + swz(row, ch));
            ldsm4(al[kst], sb + OFF_QLO + swz(row, ch));
        }
        #pragma unroll
        for (int kst = 0; kst < 2; kst++)
            #pragma unroll
            for (int p = 0; p < 4; p++) {
                unsigned bh[4], bl[4];
                const int brow = (2*p + (lane >> 4)) * 8 + (lane & 7);
                const int bch  = kst*2 + ((lane >> 3) & 1);
                ldsm4(bh, sb + OFF_KHI + swz(brow, bch));
                ldsm4(bl, sb + OFF_KLO + swz(brow, bch));
                #pragma unroll
                for (int t2 = 0; t2 < 2; t2++) {
                    mma16816(qk[2*p+t2], ah[kst], &bh[2*t2]);
                    mma16816(qk[2*p+t2], al[kst], &bh[2*t2]);
                    mma16816(qk[2*p+t2], ah[kst], &bl[2*t2]);
                }
            }
    }
    __syncthreads();

    float* Lp = g_L + ((size_t)bw*8 + g)*3136;
    #pragma unroll
    for (int nt = 0; nt < 7; nt++) {
        const int j0 = nt*8 + fc;
        #pragma unroll
        for (int half = 0; half < 2; half++) {
            const int i = mrow0 + fr + half*8;
            if (i < 56) {
                const int dq = 55 + i - j0;
                float2 o;
                o.x = sqk*qk[nt][half*2+0] + sqr*qrs[i*114 + dq]
                    + skr*krs[j0*114 + 55 + j0 - i] + tsum;
                o.y = sqk*qk[nt][half*2+1] + sqr*qrs[i*114 + dq - 1]
                    + skr*krs[(j0+1)*114 + 56 + j0 - i] + tsum;
                *(float2*)&Lp[i*56 + j0] = o;
            }
        }
    }
}

// ---------------------------------------------------------------------------
// k3: softmax over w (axis=-2), in place
// ---------------------------------------------------------------------------
__global__ __launch_bounds__(64) void softmax_kernel()
{
    const int t  = threadIdx.x;
    const int ij = blockIdx.x * 64 + t;
    const int g  = blockIdx.y;
    const int b  = blockIdx.z;
    float* base = g_L + ((size_t)b*448 + g)*3136 + ij;
    const int ws = 8*3136;

    float v[56];
    float mx = -3.4e38f;
    #pragma unroll
    for (int w = 0; w < 56; w++) { v[w] = base[w*ws]; mx = fmaxf(mx, v[w]); }
    float s = 0.f;
    #pragma unroll
    for (int w = 0; w < 56; w++) { v[w] = __expf(v[w] - mx); s += v[w]; }
    const float inv = 1.f / s;
    #pragma unroll
    for (int w = 0; w < 56; w++) base[w*ws] = v[w] * inv;
}

// ---------------------------------------------------------------------------
// k4: attention output via mma.sync, one block per (b,w,g), 128 threads.
//   acc1 = sim[64x64] * Vt^T  (Vt = V^T [c][j])
//   acc2 = S'[64x112] * VR^T  (S'[i][d]=sim[i][i+d-55], VR = vrel^T [c][d])
//   out = acc1*s1+t1 + acc2*s2+t2
// smem layout (bytes):
//   0      SIMh [64x64 bf16]   8192    (later reused as vrel fp32 staging)
//   8192   SIMl                8192
//   16384  Vth  [64x64]        8192
//   24576  Vtl                 8192
//   32768  SPh  [64x112 -> 128 prows x 128B] 16384
//   49152  SPl                 16384
//   65536  VRh  (init: V fp32 staging [56][65])  16384
//   81920  VRl                 16384
//   98304  BN tables s1,t1,s2,t2 [64] each = 1024
// ---------------------------------------------------------------------------
#define AO_SIMH 0
#define AO_SIML 8192
#define AO_VTH  16384
#define AO_VTL  24576
#define AO_SPH  32768
#define AO_SPL  49152
#define AO_VRH  65536
#define AO_VRL  81920
#define AO_BN   98304
#define SMEM_AO 99328

__global__ __launch_bounds__(128) void attn_out_mma_kernel(
    const float* __restrict__ v_rel,
    const float* __restrict__ psv, const float* __restrict__ psve,
    float* __restrict__ out)
{
    extern __shared__ char sm[];
    const uint32_t sb = smem_u32(sm);
    const int tid = threadIdx.x;
    const int lane = tid & 31, wid = tid >> 5;
    const int bw = blockIdx.x;
    const int g  = blockIdx.y;
    const int b  = bw / 56, w = bw - b*56;

    const float* Lp   = g_L + ((size_t)bw*8 + g)*3136;
    const float* vsrc = g_V + (size_t)bw * (56*512) + g*64;

    // BN tables
    if (tid < 64) {
        const int ch = g*64 + tid;
        float* bn = (float*)(sm + AO_BN);
        const float a1 = psv[ch] * rsqrtf(psv[1536+ch] + EPS);
        bn[tid]       = a1;
        bn[64 + tid]  = psv[512+ch] - psv[1024+ch]*a1;
        const float a2 = psve[ch] * rsqrtf(psve[1536+ch] + EPS);
        bn[128 + tid] = a2;
        bn[192 + tid] = psve[512+ch] - psve[1024+ch]*a2;
    }

    // (a) zero Vt + SP regions (16384..65536), load V fp32 staging, fill SIM
    {
        const uint4 z = make_uint4(0,0,0,0);
        for (int t = tid; t < 3072; t += 128) ((uint4*)(sm + 16384))[t] = z;
        float* stg = (float*)(sm + AO_VRH);
        for (int t = tid; t < 3584; t += 128) {
            const int j = t >> 6, c = t & 63;
            stg[j*65 + c] = vsrc[j*512 + c];
        }
        for (int t = tid; t < 4096; t += 128) {
            const int i = t >> 6, j = t & 63;
            const float v = (i < 56 && j < 56) ? Lp[i*56 + j] : 0.f;
            __nv_bfloat16 h, l; split1(v, h, l);
            const uint32_t o = swz128(i, j >> 3) + (j & 7)*2;
            *(__nv_bfloat16*)(sm + AO_SIMH + o) = h;
            *(__nv_bfloat16*)(sm + AO_SIML + o) = l;
        }
    }
    __syncthreads();

    // (b) transpose V -> Vt bf16 hi/lo; scatter sim -> SP (banded -> dense)
    {
        const float* stg = (const float*)(sm + AO_VRH);
        const int c = tid & 63, half = tid >> 6;
        #pragma unroll
        for (int jj = 0; jj < 28; jj++) {
            const int j = half*28 + jj;
            const float v = stg[j*65 + c];
            __nv_bfloat16 h, l; split1(v, h, l);
            const uint32_t o = swz128(c, j >> 3) + (j & 7)*2;
            *(__nv_bfloat16*)(sm + AO_VTH + o) = h;
            *(__nv_bfloat16*)(sm + AO_VTL + o) = l;
        }
        for (int t = tid; t < 3136; t += 128) {
            const int i = t / 56, j = t - i*56;
            const float v = Lp[t];
            __nv_bfloat16 h, l; split1(v, h, l);
            const int d = 55 + j - i;
            const int prow = 2*i + (d >> 6);
            const int ch = (d & 63) >> 3;
            const uint32_t o = (uint32_t)(prow*128 + ((ch ^ (i & 7)) << 4) + (d & 7)*2);
            *(__nv_bfloat16*)(sm + AO_SPH + o) = h;
            *(__nv_bfloat16*)(sm + AO_SPL + o) = l;
        }
    }
    __syncthreads();

    // (c) phase-1 mma: acc1 = sim * V
    float acc1[8][4], acc2[8][4];
    #pragma unroll
    for (int nt = 0; nt < 8; nt++)
        #pragma unroll
        for (int c = 0; c < 4; c++) { acc1[nt][c] = 0.f; acc2[nt][c] = 0.f; }

    #pragma unroll
    for (int kst = 0; kst < 4; kst++) {
        unsigned ah[4], al[4];
        {
            const int row = wid*16 + (lane & 15);
            const int ch  = kst*2 + (lane >> 4);
            const uint32_t ad = sb + AO_SIMH + swz128(row, ch);
            ldsm4(ah, ad);
            ldsm4(al, ad + 8192);
        }
        unsigned bh[16], bl[16];
        #pragma unroll
        for (int p = 0; p < 4; p++) {
            const int row = (2*p + (lane >> 4))*8 + (lane & 7);
            const int ch  = kst*2 + ((lane >> 3) & 1);
            const uint32_t bd = sb + AO_VTH + swz128(row, ch);
            ldsm4(&bh[p*4], bd);
            ldsm4(&bl[p*4], bd + 8192);
        }
        #pragma unroll
        for (int nt = 0; nt < 8; nt++) {
            mma16816(acc1[nt], ah, &bh[nt*2]);
            mma16816(acc1[nt], al, &bh[nt*2]);
            mma16816(acc1[nt], ah, &bl[nt*2]);
        }
    }
    __syncthreads();

    // (d) load vrel fp32 staging into SIM region (now free)
    {
        float* stg2 = (float*)(sm + AO_SIMH);
        for (int t = tid; t < 7104; t += 128) {
            const int d = t >> 6, c = t & 63;
            stg2[d*65 + c] = v_rel[t];
        }
    }
    __syncthreads();

    // (e) transpose vrel -> VR bf16 hi/lo [c rows][d cols 0..111], col 111 zero-pad
    {
        const float* stg2 = (const float*)(sm + AO_SIMH);
        const int c = tid & 63, half = tid >> 6;
        #pragma unroll
        for (int dd = 0; dd < 56; dd++) {
            const int d = half*56 + dd;
            const float v = (d < 111) ? stg2[d*65 + c] : 0.f;
            __nv_bfloat16 h, l; split1(v, h, l);
            const int prow = 2*c + (d >> 6);
            const int ch = (d & 63) >> 3;
            const uint32_t o = (uint32_t)(prow*128 + ((ch ^ (c & 7)) << 4) + (d & 7)*2);
            *(__nv_bfloat16*)(sm + AO_VRH + o) = h;
            *(__nv_bfloat16*)(sm + AO_VRL + o) = l;
        }
    }
    __syncthreads();

    // (f) phase-2 mma: acc2 = S' * vrel
    #pragma unroll
    for (int kst = 0; kst < 7; kst++) {
        unsigned ah[4], al[4];
        {
            const int lrow = wid*16 + (lane & 15);
            const int kloc = kst*16 + (lane >> 4)*8;
            const int prow = 2*lrow + (kloc >> 6);
            const int ch = (kloc & 63) >> 3;
            const uint32_t ad = sb + AO_SPH + (uint32_t)(prow*128 + ((ch ^ (lrow & 7)) << 4));
            ldsm4(ah, ad);
            ldsm4(al, ad + 16384);
        }
        unsigned bh[16], bl[16];
        #pragma unroll
        for (int p = 0; p < 4; p++) {
            const int lrow = (2*p + (lane >> 4))*8 + (lane & 7);
            const int kloc = kst*16 + ((lane >> 3) & 1)*8;
            const int prow = 2*lrow + (kloc >> 6);
            const int ch = (kloc & 63) >> 3;
            const uint32_t bd = sb + AO_VRH + (uint32_t)(prow*128 + ((ch ^ (lrow & 7)) << 4));
            ldsm4(&bh[p*4], bd);
            ldsm4(&bl[p*4], bd + 16384);
        }
        #pragma unroll
        for (int nt = 0; nt < 8; nt++) {
            mma16816(acc2[nt], ah, &bh[nt*2]);
            mma16816(acc2[nt], al, &bh[nt*2]);
            mma16816(acc2[nt], ah, &bl[nt*2]);
        }
    }

    // (g) epilogue: out = acc1*s1 + t1 + acc2*s2 + t2
    {
        const float* bn = (const float*)(sm + AO_BN);
        const int colb = (lane & 3)*2;
        #pragma unroll
        for (int nt = 0; nt < 8; nt++) {
            const int c = nt*8 + colb;
            const float s1a = bn[c],       s1b = bn[c+1];
            const float t1a = bn[64+c],    t1b = bn[64+c+1];
            const float s2a = bn[128+c],   s2b = bn[128+c+1];
            const float t2a = bn[192+c],   t2b = bn[192+c+1];
            #pragma unroll
            for (int half = 0; half < 2; half++) {
                const int i = wid*16 + (lane >> 2) + half*8;
                if (i < 56) {
                    float2 o;
                    o.x = acc1[nt][half*2+0]*s1a + t1a + acc2[nt][half*2+0]*s2a + t2a;
                    o.y = acc1[nt][half*2+1]*s1b + t1b + acc2[nt][half*2+1]*s2b + t2b;
                    *(float2*)&out[((size_t)((b*56 + i)*56 + w))*512 + g*64 + c] = o;
                }
            }
        }
    }
}

// ---------------------------------------------------------------------------
extern "C" void kernel_launch(void* const* d_in, const int* in_sizes, int n_in,
                              void* d_out, int out_size)
{
    const float* x     = (const float*)d_in[0];
    const float* Wq    = (const float*)d_in[1];
    const float* Wk    = (const float*)d_in[2];
    const float* Wv    = (const float*)d_in[3];
    const float* q_rel = (const float*)d_in[4];
    const float* k_rel = (const float*)d_in[5];
    const float* v_rel = (const float*)d_in[6];
    const float* p_q   = (const float*)d_in[7];
    const float* p_k   = (const float*)d_in[8];
    const float* p_v   = (const float*)d_in[9];
    const float* p_qk  = (const float*)d_in[10];
    const float* p_qr  = (const float*)d_in[11];
    const float* p_kr  = (const float*)d_in[12];
    const float* p_sv  = (const float*)d_in[13];
    const float* p_sve = (const float*)d_in[14];
    float* out = (float*)d_out;

    cudaFuncSetAttribute(qkv_mma_kernel,
                         cudaFuncAttributeMaxDynamicSharedMemorySize, SMEM_MMA);
    cudaFuncSetAttribute(logits_mma_kernel,
                         cudaFuncAttributeMaxDynamicSharedMemorySize, SMEM_LOGITS);
    cudaFuncSetAttribute(attn_out_mma_kernel,
                         cudaFuncAttributeMaxDynamicSharedMemorySize, SMEM_AO);

    split_w_kernel<<<dim3(32, 16), 256>>>(Wq, Wk, Wv);
    qkv_mma_kernel<<<dim3(8, 392), 256, SMEM_MMA>>>(x, p_q, p_k, p_v);
    logits_mma_kernel<<<dim3(896, 8), 128, SMEM_LOGITS>>>(q_rel, k_rel, p_qk, p_qr, p_kr);
    softmax_kernel<<<dim3(49, 8, 16), 64>>>();
    attn_out_mma_kernel<<<dim3(896, 8), 128, SMEM_AO>>>(v_rel, p_sv, p_sve, out);
}

// round 12
// speedup vs baseline: 1.0356x; 1.0356x over previous
#include <cuda_runtime.h>
#include <cuda_bf16.h>
#include <cstdint>

// ---------------------------------------------------------------------------
// AxialAttention (K=56, G=8, CIN=512, COUT=512)
//   k0 : transpose+split W -> g_whi/g_wlo [1024 n][512 k] bf16
//   kp : precompute vrel^T bf16 hi/lo swizzled smem image (32KB, once)
//   k1 : qkv GEMM via mma.sync m16n8k16 bf16 (3-product split), inline x split
//   k2 : logits via mma.sync: QK^T + diag-gather of Q*qrel^T and K*krel^T
//   k3 : in-place softmax over w
//   k4 : attn_out via mma.sync v2: staged sim, packed bf16x2 fills, VR copy
// ---------------------------------------------------------------------------

#define EPS 1e-3f

__device__ float g_Q[12845056];   // [16][56 w][56 i][256]
__device__ float g_K[12845056];
__device__ float g_V[25690112];   // [16][56 w][56 j][512]
__device__ float g_L[22478848];   // [16][56 w][8 g][3136 ij]
__device__ __align__(16) __nv_bfloat16 g_whi[524288];    // [1024 n][512 k]
__device__ __align__(16) __nv_bfloat16 g_wlo[524288];
__device__ __align__(16) char g_vrT[32768];              // VRh(16K)+VRl(16K) smem image

__device__ __forceinline__ uint32_t smem_u32(const void* p) {
    uint32_t a;
    asm("{ .reg .u64 t; cvta.to.shared.u64 t, %1; cvt.u32.u64 %0, t; }" : "=r"(a) : "l"(p));
    return a;
}
__device__ __forceinline__ void ldsm4(unsigned* r, uint32_t a) {
    asm volatile("ldmatrix.sync.aligned.m8n8.x4.shared.b16 {%0,%1,%2,%3}, [%4];"
        : "=r"(r[0]), "=r"(r[1]), "=r"(r[2]), "=r"(r[3]) : "r"(a));
}
__device__ __forceinline__ void mma16816(float* d, const unsigned* a, const unsigned* b) {
    asm volatile("mma.sync.aligned.m16n8k16.row.col.f32.bf16.bf16.f32 "
        "{%0,%1,%2,%3}, {%4,%5,%6,%7}, {%8,%9}, {%0,%1,%2,%3};"
        : "+f"(d[0]), "+f"(d[1]), "+f"(d[2]), "+f"(d[3])
        : "r"(a[0]), "r"(a[1]), "r"(a[2]), "r"(a[3]), "r"(b[0]), "r"(b[1]));
}
// smem swizzle: rows of 32 bf16 (64B = 4 chunks of 16B)
__device__ __forceinline__ uint32_t swz(int row, int chunk) {
    return (uint32_t)(row * 64 + ((chunk ^ (row & 3) ^ ((row >> 2) & 1)) << 4));
}
// smem swizzle: rows of 64 bf16 (128B = 8 chunks of 16B)
__device__ __forceinline__ uint32_t swz128(int row, int chunk) {
    return (uint32_t)(row * 128 + ((chunk ^ (row & 7)) << 4));
}
__device__ __forceinline__ void split_pair(float a, float b, unsigned& hi2, unsigned& lo2) {
    __nv_bfloat162 h = __floats2bfloat162_rn(a, b);
    float ra = a - __bfloat162float(h.x);
    float rb = b - __bfloat162float(h.y);
    __nv_bfloat162 l = __floats2bfloat162_rn(ra, rb);
    hi2 = *(unsigned*)&h;
    lo2 = *(unsigned*)&l;
}
__device__ __forceinline__ void split8(float4 a, float4 b, uint4& hi, uint4& lo) {
    split_pair(a.x, a.y, hi.x, lo.x);
    split_pair(a.z, a.w, hi.y, lo.y);
    split_pair(b.x, b.y, hi.z, lo.z);
    split_pair(b.z, b.w, hi.w, lo.w);
}
__device__ __forceinline__ void split1(float v, __nv_bfloat16& h, __nv_bfloat16& l) {
    h = __float2bfloat16_rn(v);
    l = __float2bfloat16_rn(v - __bfloat162float(h));
}

// ---------------------------------------------------------------------------
// k0: transpose + split W -> g_whi/g_wlo [n][k]
// ---------------------------------------------------------------------------
__global__ __launch_bounds__(256) void split_w_kernel(
    const float* __restrict__ Wq, const float* __restrict__ Wk, const float* __restrict__ Wv)
{
    __shared__ float t[32][33];
    const int n0 = blockIdx.x * 32, k0 = blockIdx.y * 32;
    const float* W; int ncols, col0;
    if (n0 < 256)      { W = Wq; ncols = 256; col0 = n0;       }
    else if (n0 < 512) { W = Wk; ncols = 256; col0 = n0 - 256; }
    else               { W = Wv; ncols = 512; col0 = n0 - 512; }
    const int tx = threadIdx.x & 31, ty = threadIdx.x >> 5;
    #pragma unroll
    for (int i = 0; i < 32; i += 8)
        t[ty + i][tx] = W[(k0 + ty + i) * ncols + col0 + tx];
    __syncthreads();
    #pragma unroll
    for (int i = 0; i < 32; i += 8) {
        const float v = t[tx][ty + i];
        const __nv_bfloat16 h = __float2bfloat16_rn(v);
        g_whi[(n0 + ty + i) * 512 + k0 + tx] = h;
        g_wlo[(n0 + ty + i) * 512 + k0 + tx] = __float2bfloat16_rn(v - __bfloat162float(h));
    }
}

// ---------------------------------------------------------------------------
// kp: precompute vrel^T bf16 hi/lo swizzled smem image.
//   VR[c][d] = v_rel[d*64+c], prow = 2c + (d>>6), SW within 128B rows.
// ---------------------------------------------------------------------------
__global__ void prep_vrT_kernel(const float* __restrict__ v_rel)
{
    const int tid = threadIdx.x;
    const uint4 z = make_uint4(0,0,0,0);
    for (int t = tid; t < 2048; t += 256) ((uint4*)g_vrT)[t] = z;
    __syncthreads();
    for (int t = tid; t < 7104; t += 256) {
        const int c = t & 63, d = t >> 6;     // d 0..110
        __nv_bfloat16 h, l; split1(v_rel[d*64 + c], h, l);
        const int prow = 2*c + (d >> 6);
        const int ch = (d & 63) >> 3;
        const uint32_t o = (uint32_t)(prow*128 + ((ch ^ (c & 7)) << 4) + (d & 7)*2);
        *(__nv_bfloat16*)(g_vrT + o)         = h;
        *(__nv_bfloat16*)(g_vrT + 16384 + o) = l;
    }
}

// ---------------------------------------------------------------------------
// k1: mma.sync bf16 QKV GEMM. BM=128 BN=128 BK=32, 256 thr (8 warps, 4Mx2N)
// ---------------------------------------------------------------------------
#define STG 32768
#define SMEM_MMA (2*STG + 1024)

__global__ __launch_bounds__(256, 1) void qkv_mma_kernel(
    const float* __restrict__ x,
    const float* __restrict__ pq, const float* __restrict__ pk, const float* __restrict__ pv)
{
    extern __shared__ char smem[];
    float* Ssc = (float*)(smem + 2*STG);
    float* Tsc = Ssc + 128;

    const int tid  = threadIdx.x;
    const int lane = tid & 31, wid = tid >> 5;
    const int mbase = (wid >> 1) * 32;
    const int nbase = (wid & 1) * 64;
    const int n0 = blockIdx.x * 128;
    const int m0 = blockIdx.y * 128;
    const uint32_t sb = smem_u32(smem);

    const float* P; float* dst; int ncols, colbase;
    if (n0 < 256)      { P = pq; dst = g_Q; ncols = 256; colbase = n0;       }
    else if (n0 < 512) { P = pk; dst = g_K; ncols = 256; colbase = n0 - 256; }
    else               { P = pv; dst = g_V; ncols = 512; colbase = n0 - 512; }

    if (tid < 128) {
        const int ch = colbase + tid;
        const float s = P[ch] * rsqrtf(P[3*ncols + ch] + EPS);
        Ssc[tid] = s;
        Tsc[tid] = P[ncols + ch] - P[2*ncols + ch] * s;
    }

    const int prow = tid >> 1;
    const int pc   = (tid & 1) * 2;
    const size_t aoff = (size_t)(m0 + prow) * 512;
    const size_t boff = (size_t)(n0 + prow) * 512;
    const uint32_t so0 = swz(prow, pc), so1 = swz(prow, pc + 1);

    float acc[2][8][4];
    #pragma unroll
    for (int mt = 0; mt < 2; mt++)
        #pragma unroll
        for (int nt = 0; nt < 8; nt++)
            #pragma unroll
            for (int c = 0; c < 4; c++) acc[mt][nt][c] = 0.f;

    {
        const int koff = pc * 8;
        const float4* px = (const float4*)(x + aoff + koff);
        float4 x0 = px[0], x1 = px[1], x2 = px[2], x3 = px[3];
        uint4 h0, l0, h1, l1;
        split8(x0, x1, h0, l0);
        split8(x2, x3, h1, l1);
        const uint4* pwh = (const uint4*)(g_whi + boff + koff);
        const uint4* pwl = (const uint4*)(g_wlo + boff + koff);
        char* s = smem;
        *(uint4*)(s + so0)          = h0; *(uint4*)(s + so1)          = h1;
        *(uint4*)(s + 8192  + so0)  = l0; *(uint4*)(s + 8192  + so1)  = l1;
        *(uint4*)(s + 16384 + so0)  = pwh[0]; *(uint4*)(s + 16384 + so1) = pwh[1];
        *(uint4*)(s + 24576 + so0)  = pwl[0]; *(uint4*)(s + 24576 + so1) = pwl[1];
    }
    __syncthreads();

    for (int ks = 0; ks < 16; ks++) {
        const int cur = ks & 1;
        float4 fx[4]; uint4 fw[4];
        if (ks < 15) {
            const int koff = (ks + 1) * 32 + pc * 8;
            const float4* px = (const float4*)(x + aoff + koff);
            fx[0] = px[0]; fx[1] = px[1]; fx[2] = px[2]; fx[3] = px[3];
            const uint4* pwh = (const uint4*)(g_whi + boff + koff);
            const uint4* pwl = (const uint4*)(g_wlo + boff + koff);
            fw[0] = pwh[0]; fw[1] = pwh[1];
            fw[2] = pwl[0]; fw[3] = pwl[1];
        }
        const uint32_t stb = sb + cur * STG;
        #pragma unroll
        for (int kst = 0; kst < 2; kst++) {
            unsigned ah[2][4], al[2][4], bh[16], bl[16];
            #pragma unroll
            for (int mt = 0; mt < 2; mt++) {
                const int row = mbase + mt*16 + (lane & 15);
                const int ch  = kst*2 + (lane >> 4);
                const uint32_t ad = stb + swz(row, ch);
                ldsm4(ah[mt], ad);
                ldsm4(al[mt], ad + 8192);
            }
            #pragma unroll
            for (int p = 0; p < 4; p++) {
                const int row = nbase + (2*p + (lane >> 4)) * 8 + (lane & 7);
                const int ch  = kst*2 + ((lane >> 3) & 1);
                const uint32_t bd = stb + 16384 + swz(row, ch);
                ldsm4(&bh[p*4], bd);
                ldsm4(&bl[p*4], bd + 8192);
            }
            #pragma unroll
            for (int mt = 0; mt < 2; mt++)
                #pragma unroll
                for (int nt = 0; nt < 8; nt++) {
                    mma16816(acc[mt][nt], ah[mt], &bh[nt*2]);
                    mma16816(acc[mt][nt], al[mt], &bh[nt*2]);
                    mma16816(acc[mt][nt], ah[mt], &bl[nt*2]);
                }
        }
        __syncthreads();
        if (ks < 15) {
            uint4 h0, l0, h1, l1;
            split8(fx[0], fx[1], h0, l0);
            split8(fx[2], fx[3], h1, l1);
            char* s = smem + (cur ^ 1) * STG;
            *(uint4*)(s + so0)         = h0;    *(uint4*)(s + so1)         = h1;
            *(uint4*)(s + 8192  + so0) = l0;    *(uint4*)(s + 8192  + so1) = l1;
            *(uint4*)(s + 16384 + so0) = fw[0]; *(uint4*)(s + 16384 + so1) = fw[1];
            *(uint4*)(s + 24576 + so0) = fw[2]; *(uint4*)(s + 24576 + so1) = fw[3];
            __syncthreads();
        }
    }

    #pragma unroll
    for (int mt = 0; mt < 2; mt++) {
        #pragma unroll
        for (int half = 0; half < 2; half++) {
            const int m = m0 + mbase + mt*16 + (lane >> 2) + half*8;
            const int b = m / 3136;
            const int rem = m - b*3136;
            const int i = rem / 56;
            const int w = rem - i*56;
            float* dr = dst + (size_t)((b*56 + w)*56 + i) * ncols + colbase;
            #pragma unroll
            for (int nt = 0; nt < 8; nt++) {
                const int col = nbase + nt*8 + (lane & 3)*2;
                float2 o;
                o.x = acc[mt][nt][half*2+0] * Ssc[col]   + Tsc[col];
                o.y = acc[mt][nt][half*2+1] * Ssc[col+1] + Tsc[col+1];
                *(float2*)(dr + col) = o;
            }
        }
    }
}

// ---------------------------------------------------------------------------
// k2: logits via mma.sync. One block per (b,w,g), 128 threads (4 warps).
// ---------------------------------------------------------------------------
#define OFF_QHI  0
#define OFF_QLO  4096
#define OFF_KHI  8192
#define OFF_KLO  12288
#define OFF_RQHI 16384
#define OFF_RQLO 23552
#define OFF_RKHI 30720
#define OFF_RKLO 37888
#define OFF_QRS  45056
#define OFF_KRS  74240
#define SMEM_LOGITS 103424

__global__ __launch_bounds__(128) void logits_mma_kernel(
    const float* __restrict__ q_rel, const float* __restrict__ k_rel,
    const float* __restrict__ pqk, const float* __restrict__ pqr, const float* __restrict__ pkr)
{
    extern __shared__ char sm[];
    const uint32_t sb = smem_u32(sm);
    const int tid = threadIdx.x;
    const int lane = tid & 31, wid = tid >> 5;
    const int bw = blockIdx.x;
    const int g  = blockIdx.y;

    const float* qbase = g_Q + (size_t)bw * 56 * 256 + g * 32;
    const float* kbase = g_K + (size_t)bw * 56 * 256 + g * 32;
    for (int t = tid; t < 224; t += 128) {
        const int row = t >> 2, ch = t & 3;
        const uint32_t o = swz(row, ch);
        float4 a = *(const float4*)(qbase + row*256 + ch*8);
        float4 b = *(const float4*)(qbase + row*256 + ch*8 + 4);
        uint4 hi, lo; split8(a, b, hi, lo);
        *(uint4*)(sm + OFF_QHI + o) = hi;
        *(uint4*)(sm + OFF_QLO + o) = lo;
        a = *(const float4*)(kbase + row*256 + ch*8);
        b = *(const float4*)(kbase + row*256 + ch*8 + 4);
        split8(a, b, hi, lo);
        *(uint4*)(sm + OFF_KHI + o) = hi;
        *(uint4*)(sm + OFF_KLO + o) = lo;
    }
    for (int t = tid; t < 444; t += 128) {
        const int row = t >> 2, ch = t & 3;
        const uint32_t o = swz(row, ch);
        float4 a = *(const float4*)(q_rel + row*32 + ch*8);
        float4 b = *(const float4*)(q_rel + row*32 + ch*8 + 4);
        uint4 hi, lo; split8(a, b, hi, lo);
        *(uint4*)(sm + OFF_RQHI + o) = hi;
        *(uint4*)(sm + OFF_RQLO + o) = lo;
        a = *(const float4*)(k_rel + row*32 + ch*8);
        b = *(const float4*)(k_rel + row*32 + ch*8 + 4);
        split8(a, b, hi, lo);
        *(uint4*)(sm + OFF_RKHI + o) = hi;
        *(uint4*)(sm + OFF_RKLO + o) = lo;
    }
    __syncthreads();

    const float sqk = pqk[g] * rsqrtf(pqk[24+g] + EPS);
    const float sqr = pqr[g] * rsqrtf(pqr[24+g] + EPS);
    const float skr = pkr[g] * rsqrtf(pkr[24+g] + EPS);
    const float tsum = (pqk[8+g] - pqk[16+g]*sqk)
                     + (pqr[8+g] - pqr[16+g]*sqr)
                     + (pkr[8+g] - pkr[16+g]*skr);

    const int mrow0 = wid * 16;
    float* qrs = (float*)(sm + OFF_QRS);
    float* krs = (float*)(sm + OFF_KRS);
    const int fr = lane >> 2, fc = (lane & 3) * 2;

    {
        unsigned ah[2][4], al[2][4];
        #pragma unroll
        for (int kst = 0; kst < 2; kst++) {
            const int row = mrow0 + (lane & 15);
            const int ch  = kst*2 + (lane >> 4);
            ldsm4(ah[kst], sb + OFF_QHI + swz(row, ch));
            ldsm4(al[kst], sb + OFF_QLO + swz(row, ch));
        }
        float acc[14][4];
        #pragma unroll
        for (int nt = 0; nt < 14; nt++)
            #pragma unroll
            for (int c = 0; c < 4; c++) acc[nt][c] = 0.f;
        #pragma unroll
        for (int kst = 0; kst < 2; kst++)
            #pragma unroll
            for (int p = 0; p < 7; p++) {
                unsigned bh[4], bl[4];
                const int brow = (2*p + (lane >> 4)) * 8 + (lane & 7);
                const int bch  = kst*2 + ((lane >> 3) & 1);
                ldsm4(bh, sb + OFF_RQHI + swz(brow, bch));
                ldsm4(bl, sb + OFF_RQLO + swz(brow, bch));
                #pragma unroll
                for (int t2 = 0; t2 < 2; t2++) {
                    mma16816(acc[2*p+t2], ah[kst], &bh[2*t2]);
                    mma16816(acc[2*p+t2], al[kst], &bh[2*t2]);
                    mma16816(acc[2*p+t2], ah[kst], &bl[2*t2]);
                }
            }
        #pragma unroll
        for (int nt = 0; nt < 14; nt++) {
            *(float2*)&qrs[(mrow0+fr)*114   + nt*8 + fc] = make_float2(acc[nt][0], acc[nt][1]);
            *(float2*)&qrs[(mrow0+fr+8)*114 + nt*8 + fc] = make_float2(acc[nt][2], acc[nt][3]);
        }
    }
    {
        unsigned ah[2][4], al[2][4];
        #pragma unroll
        for (int kst = 0; kst < 2; kst++) {
            const int row = mrow0 + (lane & 15);
            const int ch  = kst*2 + (lane >> 4);
            ldsm4(ah[kst], sb + OFF_KHI + swz(row, ch));
            ldsm4(al[kst], sb + OFF_KLO + swz(row, ch));
        }
        float acc[14][4];
        #pragma unroll
        for (int nt = 0; nt < 14; nt++)
            #pragma unroll
            for (int c = 0; c < 4; c++) acc[nt][c] = 0.f;
        #pragma unroll
        for (int kst = 0; kst < 2; kst++)
            #pragma unroll
            for (int p = 0; p < 7; p++) {
                unsigned bh[4], bl[4];
                const int brow = (2*p + (lane >> 4)) * 8 + (lane & 7);
                const int bch  = kst*2 + ((lane >> 3) & 1);
                ldsm4(bh, sb + OFF_RKHI + swz(brow, bch));
                ldsm4(bl, sb + OFF_RKLO + swz(brow, bch));
                #pragma unroll
                for (int t2 = 0; t2 < 2; t2++) {
                    mma16816(acc[2*p+t2], ah[kst], &bh[2*t2]);
                    mma16816(acc[2*p+t2], al[kst], &bh[2*t2]);
                    mma16816(acc[2*p+t2], ah[kst], &bl[2*t2]);
                }
            }
        #pragma unroll
        for (int nt = 0; nt < 14; nt++) {
            *(float2*)&krs[(mrow0+fr)*114   + nt*8 + fc] = make_float2(acc[nt][0], acc[nt][1]);
            *(float2*)&krs[(mrow0+fr+8)*114 + nt*8 + fc] = make_float2(acc[nt][2], acc[nt][3]);
        }
    }
    float qk[8][4];
    #pragma unroll
    for (int nt = 0; nt < 8; nt++)
        #pragma unroll
        for (int c = 0; c < 4; c++) qk[nt][c] = 0.f;
    {
        unsigned ah[2][4], al[2][4];
        #pragma unroll
        for (int kst = 0; kst < 2; kst++) {
            const int row = mrow0 + (lane & 15);
            const int ch  = kst*2 + (lane >> 4);
            ldsm4(ah[kst], sb + OFF_QHI + swz(row, ch));
            ldsm4(al[kst], sb + OFF_QLO + swz(row, ch));
        }
        #pragma unroll
        for (int kst = 0; kst < 2; kst++)
            #pragma unroll
            for (int p = 0; p < 4; p++) {
                unsigned bh[4], bl[4];
                const int brow = (2*p + (lane >> 4)) * 8 + (lane & 7);
                const int bch  = kst*2 + ((lane >> 3) & 1);
                ldsm4(bh, sb + OFF_KHI + swz(brow, bch));
                ldsm4(bl, sb + OFF_KLO + swz(brow, bch));
                #pragma unroll
                for (int t2 = 0; t2 < 2; t2++) {
                    mma16816(qk[2*p+t2], ah[kst], &bh[2*t2]);
                    mma16816(qk[2*p+t2], al[kst], &bh[2*t2]);
                    mma16816(qk[2*p+t2], ah[kst], &bl[2*t2]);
                }
            }
    }
    __syncthreads();

    float* Lp = g_L + ((size_t)bw*8 + g)*3136;
    #pragma unroll
    for (int nt = 0; nt < 7; nt++) {
        const int j0 = nt*8 + fc;
        #pragma unroll
        for (int half = 0; half < 2; half++) {
            const int i = mrow0 + fr + half*8;
            if (i < 56) {
                const int dq = 55 + i - j0;
                float2 o;
                o.x = sqk*qk[nt][half*2+0] + sqr*qrs[i*114 + dq]
                    + skr*krs[j0*114 + 55 + j0 - i] + tsum;
                o.y = sqk*qk[nt][half*2+1] + sqr*qrs[i*114 + dq - 1]
                    + skr*krs[(j0+1)*114 + 56 + j0 - i] + tsum;
                *(float2*)&Lp[i*56 + j0] = o;
            }
        }
    }
}

// ---------------------------------------------------------------------------
// k3: softmax over w (axis=-2), in place
// ---------------------------------------------------------------------------
__global__ __launch_bounds__(64) void softmax_kernel()
{
    const int t  = threadIdx.x;
    const int ij = blockIdx.x * 64 + t;
    const int g  = blockIdx.y;
    const int b  = blockIdx.z;
    float* base = g_L + ((size_t)b*448 + g)*3136 + ij;
    const int ws = 8*3136;

    float v[56];
    float mx = -3.4e38f;
    #pragma unroll
    for (int w = 0; w < 56; w++) { v[w] = base[w*ws]; mx = fmaxf(mx, v[w]); }
    float s = 0.f;
    #pragma unroll
    for (int w = 0; w < 56; w++) { v[w] = __expf(v[w] - mx); s += v[w]; }
    const float inv = 1.f / s;
    #pragma unroll
    for (int w = 0; w < 56; w++) base[w*ws] = v[w] * inv;
}

// ---------------------------------------------------------------------------
// k4 v2: attn_out via mma.sync, one block per (b,w,g), 128 threads.
// smem: SIMh 0, SIMl 8192, Vth 16384, Vtl 24576, SPh 32768, SPl 49152,
//       VRh 65536, VRl 81920 (staging: sim fp32 @VRh [56][57], V fp32 @VRl
//       [56][65], both consumed before VR global copy), BN 98304.
// ---------------------------------------------------------------------------
#define AO_SIMH 0
#define AO_SIML 8192
#define AO_VTH  16384
#define AO_VTL  24576
#define AO_SPH  32768
#define AO_SPL  49152
#define AO_VRH  65536
#define AO_VRL  81920
#define AO_BN   98304
#define SMEM_AO 99328

__global__ __launch_bounds__(128) void attn_out_mma_kernel(
    const float* __restrict__ psv, const float* __restrict__ psve,
    float* __restrict__ out)
{
    extern __shared__ char sm[];
    const uint32_t sb = smem_u32(sm);
    const int tid = threadIdx.x;
    const int lane = tid & 31, wid = tid >> 5;
    const int bw = blockIdx.x;
    const int g  = blockIdx.y;
    const int b  = bw / 56, w = bw - b*56;

    const float* Lp   = g_L + ((size_t)bw*8 + g)*3136;
    const float* vsrc = g_V + (size_t)bw * (56*512) + g*64;
    float* simstg = (float*)(sm + AO_VRH);   // [56][57]
    float* vstg   = (float*)(sm + AO_VRL);   // [56][65]

    // p1: BN tables, zero SP, load sim + V fp32 staging
    if (tid < 64) {
        const int ch = g*64 + tid;
        float* bn = (float*)(sm + AO_BN);
        const float a1 = psv[ch] * rsqrtf(psv[1536+ch] + EPS);
        bn[tid]       = a1;
        bn[64 + tid]  = psv[512+ch] - psv[1024+ch]*a1;
        const float a2 = psve[ch] * rsqrtf(psve[1536+ch] + EPS);
        bn[128 + tid] = a2;
        bn[192 + tid] = psve[512+ch] - psve[1024+ch]*a2;
    }
    {
        const uint4 z = make_uint4(0,0,0,0);
        for (int t = tid; t < 2048; t += 128) ((uint4*)(sm + AO_SPH))[t] = z;
        for (int t = tid; t < 3136; t += 128) {
            const int i = t / 56, j = t - i*56;
            simstg[i*57 + j] = Lp[t];
        }
        for (int t = tid; t < 3584; t += 128) {
            const int j = t >> 6, c = t & 63;
            vstg[j*65 + c] = vsrc[j*512 + c];
        }
    }
    __syncthreads();

    // p2: packed bf16x2 fills of SIM, Vt, SP from smem staging
    for (int t = tid; t < 2048; t += 128) {          // SIM [64 i][64 j]
        const int i = t >> 5, j = (t & 31) * 2;
        const bool v = (i < 56) && (j < 56);
        const float a  = v ? simstg[i*57 + j]     : 0.f;
        const float bv = v ? simstg[i*57 + j + 1] : 0.f;
        unsigned h2, l2; split_pair(a, bv, h2, l2);
        const uint32_t o = swz128(i, j >> 3) + (j & 7)*2;
        *(unsigned*)(sm + AO_SIMH + o) = h2;
        *(unsigned*)(sm + AO_SIML + o) = l2;
    }
    for (int t = tid; t < 2048; t += 128) {          // Vt [64 c][64 j]
        const int c = t >> 5, j = (t & 31) * 2;
        const float a  = (j < 56) ? vstg[j*65 + c]       : 0.f;
        const float bv = (j < 56) ? vstg[(j+1)*65 + c]   : 0.f;
        unsigned h2, l2; split_pair(a, bv, h2, l2);
        const uint32_t o = swz128(c, j >> 3) + (j & 7)*2;
        *(unsigned*)(sm + AO_VTH + o) = h2;
        *(unsigned*)(sm + AO_VTL + o) = l2;
    }
    for (int t = tid; t < 3136; t += 128) {          // SP [56 i][112 d], d pairs
        const int i = t / 56, d = (t - i*56) * 2;
        const int j0 = i + d - 55;
        const float a  = ((unsigned)j0       < 56u) ? simstg[i*57 + j0]     : 0.f;
        const float bv = ((unsigned)(j0 + 1) < 56u) ? simstg[i*57 + j0 + 1] : 0.f;
        unsigned h2, l2; split_pair(a, bv, h2, l2);
        const int prow = 2*i + (d >> 6);
        const int ch = (d & 63) >> 3;
        const uint32_t o = (uint32_t)(prow*128 + ((ch ^ (i & 7)) << 4) + (d & 7)*2);
        *(unsigned*)(sm + AO_SPH + o) = h2;
        *(unsigned*)(sm + AO_SPL + o) = l2;
    }
    __syncthreads();

    // p3: VR global copy (overlaps mma1), then mma1 = SIM x Vt
    for (int t = tid; t < 2048; t += 128)
        ((uint4*)(sm + AO_VRH))[t] = ((const uint4*)g_vrT)[t];

    float acc1[8][4], acc2[8][4];
    #pragma unroll
    for (int nt = 0; nt < 8; nt++)
        #pragma unroll
        for (int c = 0; c < 4; c++) { acc1[nt][c] = 0.f; acc2[nt][c] = 0.f; }

    #pragma unroll
    for (int kst = 0; kst < 4; kst++) {
        unsigned ah[4], al[4];
        {
            const int row = wid*16 + (lane & 15);
            const int ch  = kst*2 + (lane >> 4);
            const uint32_t ad = sb + AO_SIMH + swz128(row, ch);
            ldsm4(ah, ad);
            ldsm4(al, ad + 8192);
        }
        unsigned bh[16], bl[16];
        #pragma unroll
        for (int p = 0; p < 4; p++) {
            const int row = (2*p + (lane >> 4))*8 + (lane & 7);
            const int ch  = kst*2 + ((lane >> 3) & 1);
            const uint32_t bd = sb + AO_VTH + swz128(row, ch);
            ldsm4(&bh[p*4], bd);
            ldsm4(&bl[p*4], bd + 8192);
        }
        #pragma unroll
        for (int nt = 0; nt < 8; nt++) {
            mma16816(acc1[nt], ah, &bh[nt*2]);
            mma16816(acc1[nt], al, &bh[nt*2]);
            mma16816(acc1[nt], ah, &bl[nt*2]);
        }
    }
    __syncthreads();

    // p4: mma2 = S' x VR
    #pragma unroll
    for (int kst = 0; kst < 7; kst++) {
        unsigned ah[4], al[4];
        {
            const int lrow = wid*16 + (lane & 15);
            const int kloc = kst*16 + (lane >> 4)*8;
            const int prow = 2*lrow + (kloc >> 6);
            const int ch = (kloc & 63) >> 3;
            const uint32_t ad = sb + AO_SPH + (uint32_t)(prow*128 + ((ch ^ (lrow & 7)) << 4));
            ldsm4(ah, ad);
            ldsm4(al, ad + 16384);
        }
        unsigned bh[16], bl[16];
        #pragma unroll
        for (int p = 0; p < 4; p++) {
            const int lrow = (2*p + (lane >> 4))*8 + (lane & 7);
            const int kloc = kst*16 + ((lane >> 3) & 1)*8;
            const int prow = 2*lrow + (kloc >> 6);
            const int ch = (kloc & 63) >> 3;
            const uint32_t bd = sb + AO_VRH + (uint32_t)(prow*128 + ((ch ^ (lrow & 7)) << 4));
            ldsm4(&bh[p*4], bd);
            ldsm4(&bl[p*4], bd + 16384);
        }
        #pragma unroll
        for (int nt = 0; nt < 8; nt++) {
            mma16816(acc2[nt], ah, &bh[nt*2]);
            mma16816(acc2[nt], al, &bh[nt*2]);
            mma16816(acc2[nt], ah, &bl[nt*2]);
        }
    }

    // epilogue
    {
        const float* bn = (const float*)(sm + AO_BN);
        const int colb = (lane & 3)*2;
        #pragma unroll
        for (int nt = 0; nt < 8; nt++) {
            const int c = nt*8 + colb;
            const float s1a = bn[c],       s1b = bn[c+1];
            const float t1a = bn[64+c],    t1b = bn[64+c+1];
            const float s2a = bn[128+c],   s2b = bn[128+c+1];
            const float t2a = bn[192+c],   t2b = bn[192+c+1];
            #pragma unroll
            for (int half = 0; half < 2; half++) {
                const int i = wid*16 + (lane >> 2) + half*8;
                if (i < 56) {
                    float2 o;
                    o.x = acc1[nt][half*2+0]*s1a + t1a + acc2[nt][half*2+0]*s2a + t2a;
                    o.y = acc1[nt][half*2+1]*s1b + t1b + acc2[nt][half*2+1]*s2b + t2b;
                    *(float2*)&out[((size_t)((b*56 + i)*56 + w))*512 + g*64 + c] = o;
                }
            }
        }
    }
}

// ---------------------------------------------------------------------------
extern "C" void kernel_launch(void* const* d_in, const int* in_sizes, int n_in,
                              void* d_out, int out_size)
{
    const float* x     = (const float*)d_in[0];
    const float* Wq    = (const float*)d_in[1];
    const float* Wk    = (const float*)d_in[2];
    const float* Wv    = (const float*)d_in[3];
    const float* q_rel = (const float*)d_in[4];
    const float* k_rel = (const float*)d_in[5];
    const float* v_rel = (const float*)d_in[6];
    const float* p_q   = (const float*)d_in[7];
    const float* p_k   = (const float*)d_in[8];
    const float* p_v   = (const float*)d_in[9];
    const float* p_qk  = (const float*)d_in[10];
    const float* p_qr  = (const float*)d_in[11];
    const float* p_kr  = (const float*)d_in[12];
    const float* p_sv  = (const float*)d_in[13];
    const float* p_sve = (const float*)d_in[14];
    float* out = (float*)d_out;

    cudaFuncSetAttribute(qkv_mma_kernel,
                         cudaFuncAttributeMaxDynamicSharedMemorySize, SMEM_MMA);
    cudaFuncSetAttribute(logits_mma_kernel,
                         cudaFuncAttributeMaxDynamicSharedMemorySize, SMEM_LOGITS);
    cudaFuncSetAttribute(attn_out_mma_kernel,
                         cudaFuncAttributeMaxDynamicSharedMemorySize, SMEM_AO);

    split_w_kernel<<<dim3(32, 16), 256>>>(Wq, Wk, Wv);
    prep_vrT_kernel<<<1, 256>>>(v_rel);
    qkv_mma_kernel<<<dim3(8, 392), 256, SMEM_MMA>>>(x, p_q, p_k, p_v);
    logits_mma_kernel<<<dim3(896, 8), 128, SMEM_LOGITS>>>(q_rel, k_rel, p_qk, p_qr, p_kr);
    softmax_kernel<<<dim3(49, 8, 16), 64>>>();
    attn_out_mma_kernel<<<dim3(896, 8), 128, SMEM_AO>>>(p_sv, p_sve, out);
}

// round 13
// speedup vs baseline: 1.0700x; 1.0332x over previous
#include <cuda_runtime.h>
#include <cuda_bf16.h>
#include <cstdint>

// ---------------------------------------------------------------------------
// AxialAttention (K=56, G=8, CIN=512, COUT=512)
//   k0 : transpose+split W -> g_whi/g_wlo [1024 n][512 k] bf16
//   kr : precompute rel tables bf16 hi/lo swizzled smem image (28KB, once)
//   k1 : qkv GEMM via mma.sync m16n8k16 bf16 (3-product split), inline x split
//   k2 : logits via mma.sync: QK^T + diag-gather of Q*qrel^T and K*krel^T
//   k3 : in-place softmax over w
//   k4 : attn_out SIMT per (b,w,g)  (measured-fastest variant)
// ---------------------------------------------------------------------------

#define EPS 1e-3f

__device__ float g_Q[12845056];   // [16][56 w][56 i][256]
__device__ float g_K[12845056];
__device__ float g_V[25690112];   // [16][56 w][56 j][512]
__device__ float g_L[22478848];   // [16][56 w][8 g][3136 ij]
__device__ __align__(16) __nv_bfloat16 g_whi[524288];    // [1024 n][512 k]
__device__ __align__(16) __nv_bfloat16 g_wlo[524288];
__device__ __align__(16) char g_relT[28672];  // RQhi|RQlo|RKhi|RKlo swizzled, 7168B each

__device__ __forceinline__ float dot4(float4 a, float4 b) {
    return a.x*b.x + a.y*b.y + a.z*b.z + a.w*b.w;
}
__device__ __forceinline__ uint32_t smem_u32(const void* p) {
    uint32_t a;
    asm("{ .reg .u64 t; cvta.to.shared.u64 t, %1; cvt.u32.u64 %0, t; }" : "=r"(a) : "l"(p));
    return a;
}
__device__ __forceinline__ void ldsm4(unsigned* r, uint32_t a) {
    asm volatile("ldmatrix.sync.aligned.m8n8.x4.shared.b16 {%0,%1,%2,%3}, [%4];"
        : "=r"(r[0]), "=r"(r[1]), "=r"(r[2]), "=r"(r[3]) : "r"(a));
}
__device__ __forceinline__ void mma16816(float* d, const unsigned* a, const unsigned* b) {
    asm volatile("mma.sync.aligned.m16n8k16.row.col.f32.bf16.bf16.f32 "
        "{%0,%1,%2,%3}, {%4,%5,%6,%7}, {%8,%9}, {%0,%1,%2,%3};"
        : "+f"(d[0]), "+f"(d[1]), "+f"(d[2]), "+f"(d[3])
        : "r"(a[0]), "r"(a[1]), "r"(a[2]), "r"(a[3]), "r"(b[0]), "r"(b[1]));
}
// smem swizzle: rows of 32 bf16 (64B = 4 chunks of 16B)
__device__ __forceinline__ uint32_t swz(int row, int chunk) {
    return (uint32_t)(row * 64 + ((chunk ^ (row & 3) ^ ((row >> 2) & 1)) << 4));
}
__device__ __forceinline__ void split_pair(float a, float b, unsigned& hi2, unsigned& lo2) {
    __nv_bfloat162 h = __floats2bfloat162_rn(a, b);
    float ra = a - __bfloat162float(h.x);
    float rb = b - __bfloat162float(h.y);
    __nv_bfloat162 l = __floats2bfloat162_rn(ra, rb);
    hi2 = *(unsigned*)&h;
    lo2 = *(unsigned*)&l;
}
__device__ __forceinline__ void split8(float4 a, float4 b, uint4& hi, uint4& lo) {
    split_pair(a.x, a.y, hi.x, lo.x);
    split_pair(a.z, a.w, hi.y, lo.y);
    split_pair(b.x, b.y, hi.z, lo.z);
    split_pair(b.z, b.w, hi.w, lo.w);
}

// ---------------------------------------------------------------------------
// k0: transpose + split W -> g_whi/g_wlo [n][k]
// ---------------------------------------------------------------------------
__global__ __launch_bounds__(256) void split_w_kernel(
    const float* __restrict__ Wq, const float* __restrict__ Wk, const float* __restrict__ Wv)
{
    __shared__ float t[32][33];
    const int n0 = blockIdx.x * 32, k0 = blockIdx.y * 32;
    const float* W; int ncols, col0;
    if (n0 < 256)      { W = Wq; ncols = 256; col0 = n0;       }
    else if (n0 < 512) { W = Wk; ncols = 256; col0 = n0 - 256; }
    else               { W = Wv; ncols = 512; col0 = n0 - 512; }
    const int tx = threadIdx.x & 31, ty = threadIdx.x >> 5;
    #pragma unroll
    for (int i = 0; i < 32; i += 8)
        t[ty + i][tx] = W[(k0 + ty + i) * ncols + col0 + tx];
    __syncthreads();
    #pragma unroll
    for (int i = 0; i < 32; i += 8) {
        const float v = t[tx][ty + i];
        const __nv_bfloat16 h = __float2bfloat16_rn(v);
        g_whi[(n0 + ty + i) * 512 + k0 + tx] = h;
        g_wlo[(n0 + ty + i) * 512 + k0 + tx] = __float2bfloat16_rn(v - __bfloat162float(h));
    }
}

// ---------------------------------------------------------------------------
// kr: precompute swizzled bf16 hi/lo images of q_rel / k_rel (111 x 32)
// ---------------------------------------------------------------------------
__global__ void prep_rel_kernel(const float* __restrict__ q_rel,
                                const float* __restrict__ k_rel)
{
    const int tid = threadIdx.x;
    const uint4 z = make_uint4(0,0,0,0);
    for (int t = tid; t < 1792; t += 256) ((uint4*)g_relT)[t] = z;
    __syncthreads();
    for (int t = tid; t < 444; t += 256) {
        const int row = t >> 2, ch = t & 3;
        const uint32_t o = swz(row, ch);
        float4 a = *(const float4*)(q_rel + row*32 + ch*8);
        float4 b = *(const float4*)(q_rel + row*32 + ch*8 + 4);
        uint4 hi, lo; split8(a, b, hi, lo);
        *(uint4*)(g_relT + o)         = hi;
        *(uint4*)(g_relT + 7168 + o)  = lo;
        a = *(const float4*)(k_rel + row*32 + ch*8);
        b = *(const float4*)(k_rel + row*32 + ch*8 + 4);
        split8(a, b, hi, lo);
        *(uint4*)(g_relT + 14336 + o) = hi;
        *(uint4*)(g_relT + 21504 + o) = lo;
    }
}

// ---------------------------------------------------------------------------
// k1: mma.sync bf16 QKV GEMM. BM=128 BN=128 BK=32, 256 thr (8 warps, 4Mx2N)
// ---------------------------------------------------------------------------
#define STG 32768
#define SMEM_MMA (2*STG + 1024)

__global__ __launch_bounds__(256, 1) void qkv_mma_kernel(
    const float* __restrict__ x,
    const float* __restrict__ pq, const float* __restrict__ pk, const float* __restrict__ pv)
{
    extern __shared__ char smem[];
    float* Ssc = (float*)(smem + 2*STG);
    float* Tsc = Ssc + 128;

    const int tid  = threadIdx.x;
    const int lane = tid & 31, wid = tid >> 5;
    const int mbase = (wid >> 1) * 32;
    const int nbase = (wid & 1) * 64;
    const int n0 = blockIdx.x * 128;
    const int m0 = blockIdx.y * 128;
    const uint32_t sb = smem_u32(smem);

    const float* P; float* dst; int ncols, colbase;
    if (n0 < 256)      { P = pq; dst = g_Q; ncols = 256; colbase = n0;       }
    else if (n0 < 512) { P = pk; dst = g_K; ncols = 256; colbase = n0 - 256; }
    else               { P = pv; dst = g_V; ncols = 512; colbase = n0 - 512; }

    if (tid < 128) {
        const int ch = colbase + tid;
        const float s = P[ch] * rsqrtf(P[3*ncols + ch] + EPS);
        Ssc[tid] = s;
        Tsc[tid] = P[ncols + ch] - P[2*ncols + ch] * s;
    }

    const int prow = tid >> 1;
    const int pc   = (tid & 1) * 2;
    const size_t aoff = (size_t)(m0 + prow) * 512;
    const size_t boff = (size_t)(n0 + prow) * 512;
    const uint32_t so0 = swz(prow, pc), so1 = swz(prow, pc + 1);

    float acc[2][8][4];
    #pragma unroll
    for (int mt = 0; mt < 2; mt++)
        #pragma unroll
        for (int nt = 0; nt < 8; nt++)
            #pragma unroll
            for (int c = 0; c < 4; c++) acc[mt][nt][c] = 0.f;

    {
        const int koff = pc * 8;
        const float4* px = (const float4*)(x + aoff + koff);
        float4 x0 = px[0], x1 = px[1], x2 = px[2], x3 = px[3];
        uint4 h0, l0, h1, l1;
        split8(x0, x1, h0, l0);
        split8(x2, x3, h1, l1);
        const uint4* pwh = (const uint4*)(g_whi + boff + koff);
        const uint4* pwl = (const uint4*)(g_wlo + boff + koff);
        char* s = smem;
        *(uint4*)(s + so0)          = h0; *(uint4*)(s + so1)          = h1;
        *(uint4*)(s + 8192  + so0)  = l0; *(uint4*)(s + 8192  + so1)  = l1;
        *(uint4*)(s + 16384 + so0)  = pwh[0]; *(uint4*)(s + 16384 + so1) = pwh[1];
        *(uint4*)(s + 24576 + so0)  = pwl[0]; *(uint4*)(s + 24576 + so1) = pwl[1];
    }
    __syncthreads();

    for (int ks = 0; ks < 16; ks++) {
        const int cur = ks & 1;
        float4 fx[4]; uint4 fw[4];
        if (ks < 15) {
            const int koff = (ks + 1) * 32 + pc * 8;
            const float4* px = (const float4*)(x + aoff + koff);
            fx[0] = px[0]; fx[1] = px[1]; fx[2] = px[2]; fx[3] = px[3];
            const uint4* pwh = (const uint4*)(g_whi + boff + koff);
            const uint4* pwl = (const uint4*)(g_wlo + boff + koff);
            fw[0] = pwh[0]; fw[1] = pwh[1];
            fw[2] = pwl[0]; fw[3] = pwl[1];
        }
        const uint32_t stb = sb + cur * STG;
        #pragma unroll
        for (int kst = 0; kst < 2; kst++) {
            unsigned ah[2][4], al[2][4], bh[16], bl[16];
            #pragma unroll
            for (int mt = 0; mt < 2; mt++) {
                const int row = mbase + mt*16 + (lane & 15);
                const int ch  = kst*2 + (lane >> 4);
                const uint32_t ad = stb + swz(row, ch);
                ldsm4(ah[mt], ad);
                ldsm4(al[mt], ad + 8192);
            }
            #pragma unroll
            for (int p = 0; p < 4; p++) {
                const int row = nbase + (2*p + (lane >> 4)) * 8 + (lane & 7);
                const int ch  = kst*2 + ((lane >> 3) & 1);
                const uint32_t bd = stb + 16384 + swz(row, ch);
                ldsm4(&bh[p*4], bd);
                ldsm4(&bl[p*4], bd + 8192);
            }
            #pragma unroll
            for (int mt = 0; mt < 2; mt++)
                #pragma unroll
                for (int nt = 0; nt < 8; nt++) {
                    mma16816(acc[mt][nt], ah[mt], &bh[nt*2]);
                    mma16816(acc[mt][nt], al[mt], &bh[nt*2]);
                    mma16816(acc[mt][nt], ah[mt], &bl[nt*2]);
                }
        }
        __syncthreads();
        if (ks < 15) {
            uint4 h0, l0, h1, l1;
            split8(fx[0], fx[1], h0, l0);
            split8(fx[2], fx[3], h1, l1);
            char* s = smem + (cur ^ 1) * STG;
            *(uint4*)(s + so0)         = h0;    *(uint4*)(s + so1)         = h1;
            *(uint4*)(s + 8192  + so0) = l0;    *(uint4*)(s + 8192  + so1) = l1;
            *(uint4*)(s + 16384 + so0) = fw[0]; *(uint4*)(s + 16384 + so1) = fw[1];
            *(uint4*)(s + 24576 + so0) = fw[2]; *(uint4*)(s + 24576 + so1) = fw[3];
            __syncthreads();
        }
    }

    #pragma unroll
    for (int mt = 0; mt < 2; mt++) {
        #pragma unroll
        for (int half = 0; half < 2; half++) {
            const int m = m0 + mbase + mt*16 + (lane >> 2) + half*8;
            const int b = m / 3136;
            const int rem = m - b*3136;
            const int i = rem / 56;
            const int w = rem - i*56;
            float* dr = dst + (size_t)((b*56 + w)*56 + i) * ncols + colbase;
            #pragma unroll
            for (int nt = 0; nt < 8; nt++) {
                const int col = nbase + nt*8 + (lane & 3)*2;
                float2 o;
                o.x = acc[mt][nt][half*2+0] * Ssc[col]   + Tsc[col];
                o.y = acc[mt][nt][half*2+1] * Ssc[col+1] + Tsc[col+1];
                *(float2*)(dr + col) = o;
            }
        }
    }
}

// ---------------------------------------------------------------------------
// k2: logits via mma.sync. One block per (b,w,g), 128 threads (4 warps).
// ---------------------------------------------------------------------------
#define OFF_QHI  0
#define OFF_QLO  4096
#define OFF_KHI  8192
#define OFF_KLO  12288
#define OFF_RQHI 16384
#define OFF_RQLO 23552
#define OFF_RKHI 30720
#define OFF_RKLO 37888
#define OFF_QRS  45056
#define OFF_KRS  74240
#define SMEM_LOGITS 103424

__global__ __launch_bounds__(128) void logits_mma_kernel(
    const float* __restrict__ pqk, const float* __restrict__ pqr, const float* __restrict__ pkr)
{
    extern __shared__ char sm[];
    const uint32_t sb = smem_u32(sm);
    const int tid = threadIdx.x;
    const int lane = tid & 31, wid = tid >> 5;
    const int bw = blockIdx.x;
    const int g  = blockIdx.y;

    const float* qbase = g_Q + (size_t)bw * 56 * 256 + g * 32;
    const float* kbase = g_K + (size_t)bw * 56 * 256 + g * 32;
    for (int t = tid; t < 224; t += 128) {
        const int row = t >> 2, ch = t & 3;
        const uint32_t o = swz(row, ch);
        float4 a = *(const float4*)(qbase + row*256 + ch*8);
        float4 b = *(const float4*)(qbase + row*256 + ch*8 + 4);
        uint4 hi, lo; split8(a, b, hi, lo);
        *(uint4*)(sm + OFF_QHI + o) = hi;
        *(uint4*)(sm + OFF_QLO + o) = lo;
        a = *(const float4*)(kbase + row*256 + ch*8);
        b = *(const float4*)(kbase + row*256 + ch*8 + 4);
        split8(a, b, hi, lo);
        *(uint4*)(sm + OFF_KHI + o) = hi;
        *(uint4*)(sm + OFF_KLO + o) = lo;
    }
    // copy precomputed rel images (28672B contiguous at OFF_RQHI)
    for (int t = tid; t < 1792; t += 128)
        ((uint4*)(sm + OFF_RQHI))[t] = ((const uint4*)g_relT)[t];
    __syncthreads();

    const float sqk = pqk[g] * rsqrtf(pqk[24+g] + EPS);
    const float sqr = pqr[g] * rsqrtf(pqr[24+g] + EPS);
    const float skr = pkr[g] * rsqrtf(pkr[24+g] + EPS);
    const float tsum = (pqk[8+g] - pqk[16+g]*sqk)
                     + (pqr[8+g] - pqr[16+g]*sqr)
                     + (pkr[8+g] - pkr[16+g]*skr);

    const int mrow0 = wid * 16;
    float* qrs = (float*)(sm + OFF_QRS);
    float* krs = (float*)(sm + OFF_KRS);
    const int fr = lane >> 2, fc = (lane & 3) * 2;

    {
        unsigned ah[2][4], al[2][4];
        #pragma unroll
        for (int kst = 0; kst < 2; kst++) {
            const int row = mrow0 + (lane & 15);
            const int ch  = kst*2 + (lane >> 4);
            ldsm4(ah[kst], sb + OFF_QHI + swz(row, ch));
            ldsm4(al[kst], sb + OFF_QLO + swz(row, ch));
        }
        float acc[14][4];
        #pragma unroll
        for (int nt = 0; nt < 14; nt++)
            #pragma unroll
            for (int c = 0; c < 4; c++) acc[nt][c] = 0.f;
        #pragma unroll
        for (int kst = 0; kst < 2; kst++)
            #pragma unroll
            for (int p = 0; p < 7; p++) {
                unsigned bh[4], bl[4];
                const int brow = (2*p + (lane >> 4)) * 8 + (lane & 7);
                const int bch  = kst*2 + ((lane >> 3) & 1);
                ldsm4(bh, sb + OFF_RQHI + swz(brow, bch));
                ldsm4(bl, sb + OFF_RQLO + swz(brow, bch));
                #pragma unroll
                for (int t2 = 0; t2 < 2; t2++) {
                    mma16816(acc[2*p+t2], ah[kst], &bh[2*t2]);
                    mma16816(acc[2*p+t2], al[kst], &bh[2*t2]);
                    mma16816(acc[2*p+t2], ah[kst], &bl[2*t2]);
                }
            }
        #pragma unroll
        for (int nt = 0; nt < 14; nt++) {
            *(float2*)&qrs[(mrow0+fr)*114   + nt*8 + fc] = make_float2(acc[nt][0], acc[nt][1]);
            *(float2*)&qrs[(mrow0+fr+8)*114 + nt*8 + fc] = make_float2(acc[nt][2], acc[nt][3]);
        }
    }
    {
        unsigned ah[2][4], al[2][4];
        #pragma unroll
        for (int kst = 0; kst < 2; kst++) {
            const int row = mrow0 + (lane & 15);
            const int ch  = kst*2 + (lane >> 4);
            ldsm4(ah[kst], sb + OFF_KHI + swz(row, ch));
            ldsm4(al[kst], sb + OFF_KLO + swz(row, ch));
        }
        float acc[14][4];
        #pragma unroll
        for (int nt = 0; nt < 14; nt++)
            #pragma unroll
            for (int c = 0; c < 4; c++) acc[nt][c] = 0.f;
        #pragma unroll
        for (int kst = 0; kst < 2; kst++)
            #pragma unroll
            for (int p = 0; p < 7; p++) {
                unsigned bh[4], bl[4];
                const int brow = (2*p + (lane >> 4)) * 8 + (lane & 7);
                const int bch  = kst*2 + ((lane >> 3) & 1);
                ldsm4(bh, sb + OFF_RKHI + swz(brow, bch));
                ldsm4(bl, sb + OFF_RKLO + swz(brow, bch));
                #pragma unroll
                for (int t2 = 0; t2 < 2; t2++) {
                    mma16816(acc[2*p+t2], ah[kst], &bh[2*t2]);
                    mma16816(acc[2*p+t2], al[kst], &bh[2*t2]);
                    mma16816(acc[2*p+t2], ah[kst], &bl[2*t2]);
                }
            }
        #pragma unroll
        for (int nt = 0; nt < 14; nt++) {
            *(float2*)&krs[(mrow0+fr)*114   + nt*8 + fc] = make_float2(acc[nt][0], acc[nt][1]);
            *(float2*)&krs[(mrow0+fr+8)*114 + nt*8 + fc] = make_float2(acc[nt][2], acc[nt][3]);
        }
    }
    float qk[8][4];
    #pragma unroll
    for (int nt = 0; nt < 8; nt++)
        #pragma unroll
        for (int c = 0; c < 4; c++) qk[nt][c] = 0.f;
    {
        unsigned ah[2][4], al[2][4];
        #pragma unroll
        for (int kst = 0; kst < 2; kst++) {
            const int row = mrow0 + (lane & 15);
            const int ch  = kst*2 + (lane >> 4);
            ldsm4(ah[kst], sb + OFF_QHI + swz(row, ch));
            ldsm4(al[kst], sb + OFF_QLO + swz(row, ch));
        }
        #pragma unroll
        for (int kst = 0; kst < 2; kst++)
            #pragma unroll
            for (int p = 0; p < 4; p++) {
                unsigned bh[4], bl[4];
                const int brow = (2*p + (lane >> 4)) * 8 + (lane & 7);
                const int bch  = kst*2 + ((lane >> 3) & 1);
                ldsm4(bh, sb + OFF_KHI + swz(brow, bch));
                ldsm4(bl, sb + OFF_KLO + swz(brow, bch));
                #pragma unroll
                for (int t2 = 0; t2 < 2; t2++) {
                    mma16816(qk[2*p+t2], ah[kst], &bh[2*t2]);
                    mma16816(qk[2*p+t2], al[kst], &bh[2*t2]);
                    mma16816(qk[2*p+t2], ah[kst], &bl[2*t2]);
                }
            }
    }
    __syncthreads();

    float* Lp = g_L + ((size_t)bw*8 + g)*3136;
    #pragma unroll
    for (int nt = 0; nt < 7; nt++) {
        const int j0 = nt*8 + fc;
        #pragma unroll
        for (int half = 0; half < 2; half++) {
            const int i = mrow0 + fr + half*8;
            if (i < 56) {
                const int dq = 55 + i - j0;
                float2 o;
                o.x = sqk*qk[nt][half*2+0] + sqr*qrs[i*114 + dq]
                    + skr*krs[j0*114 + 55 + j0 - i] + tsum;
                o.y = sqk*qk[nt][half*2+1] + sqr*qrs[i*114 + dq - 1]
                    + skr*krs[(j0+1)*114 + 56 + j0 - i] + tsum;
                *(float2*)&Lp[i*56 + j0] = o;
            }
        }
    }
}

// ---------------------------------------------------------------------------
// k3: softmax over w (axis=-2), in place
// ---------------------------------------------------------------------------
__global__ __launch_bounds__(64) void softmax_kernel()
{
    const int t  = threadIdx.x;
    const int ij = blockIdx.x * 64 + t;
    const int g  = blockIdx.y;
    const int b  = blockIdx.z;
    float* base = g_L + ((size_t)b*448 + g)*3136 + ij;
    const int ws = 8*3136;

    float v[56];
    float mx = -3.4e38f;
    #pragma unroll
    for (int w = 0; w < 56; w++) { v[w] = base[w*ws]; mx = fmaxf(mx, v[w]); }
    float s = 0.f;
    #pragma unroll
    for (int w = 0; w < 56; w++) { v[w] = __expf(v[w] - mx); s += v[w]; }
    const float inv = 1.f / s;
    #pragma unroll
    for (int w = 0; w < 56; w++) base[w*ws] = v[w] * inv;
}

// ---------------------------------------------------------------------------
// k4: attention output per (b,w,g) — SIMT (measured fastest)
// ---------------------------------------------------------------------------
__global__ __launch_bounds__(256) void attn_out_kernel(
    const float* __restrict__ v_rel,
    const float* __restrict__ psv, const float* __restrict__ psve,
    float* __restrict__ out)
{
    extern __shared__ float smf[];
    float* Vg     = smf;              // [56][64]
    float* vrel_s = smf + 3584;       // [111][64]
    float* sim_s  = smf + 10688;      // [56][56]

    const int tid = threadIdx.x;
    const int bw  = blockIdx.x;
    const int g   = blockIdx.y;
    const int b   = bw / 56, w = bw - b*56;

    const float* vsrc = g_V + (size_t)bw * (56*512) + g*64;
    for (int idx = tid; idx < 3584; idx += 256) {
        const int j = idx >> 6, c = idx & 63;
        Vg[idx] = vsrc[j*512 + c];
    }
    for (int idx = tid; idx < 7104; idx += 256) vrel_s[idx] = v_rel[idx];
    const float* simsrc = g_L + ((size_t)bw*8 + g)*3136;
    for (int idx = tid; idx < 3136; idx += 256) sim_s[idx] = simsrc[idx];
    __syncthreads();

    if (tid >= 224) return;
    const int ti = tid >> 4, tc = tid & 15;
    const int i0 = ti*4, c0 = tc*4;
    const int ch0 = g*64 + c0;

    float asv[4][4], asve[4][4];
    #pragma unroll
    for (int a = 0; a < 4; a++)
        #pragma unroll
        for (int c = 0; c < 4; c++) { asv[a][c]=0.f; asve[a][c]=0.f; }

    #pragma unroll 4
    for (int j = 0; j < 56; j++) {
        const float4 vv = *(const float4*)&Vg[j*64 + c0];
        #pragma unroll
        for (int a = 0; a < 4; a++) {
            const float s = sim_s[(i0+a)*56 + j];
            asv[a][0] = fmaf(s, vv.x, asv[a][0]);
            asv[a][1] = fmaf(s, vv.y, asv[a][1]);
            asv[a][2] = fmaf(s, vv.z, asv[a][2]);
            asv[a][3] = fmaf(s, vv.w, asv[a][3]);
        }
    }
    for (int d = 52 - i0; d <= 110 - i0; d++) {
        const float4 vr = *(const float4*)&vrel_s[d*64 + c0];
        #pragma unroll
        for (int a = 0; a < 4; a++) {
            const int j = i0 + a + d - 55;
            if ((unsigned)j < 56u) {
                const float s = sim_s[(i0+a)*56 + j];
                asve[a][0] = fmaf(s, vr.x, asve[a][0]);
                asve[a][1] = fmaf(s, vr.y, asve[a][1]);
                asve[a][2] = fmaf(s, vr.z, asve[a][2]);
                asve[a][3] = fmaf(s, vr.w, asve[a][3]);
            }
        }
    }

    float s1[4], t1[4], s2[4], t2[4];
    #pragma unroll
    for (int cc = 0; cc < 4; cc++) {
        const int ch = ch0 + cc;
        const float a1 = psv[ch] * rsqrtf(psv[1536+ch] + EPS);
        s1[cc] = a1; t1[cc] = psv[512+ch] - psv[1024+ch]*a1;
        const float a2 = psve[ch] * rsqrtf(psve[1536+ch] + EPS);
        s2[cc] = a2; t2[cc] = psve[512+ch] - psve[1024+ch]*a2;
    }
    #pragma unroll
    for (int a = 0; a < 4; a++) {
        float4 o;
        o.x = asv[a][0]*s1[0] + t1[0] + asve[a][0]*s2[0] + t2[0];
        o.y = asv[a][1]*s1[1] + t1[1] + asve[a][1]*s2[1] + t2[1];
        o.z = asv[a][2]*s1[2] + t1[2] + asve[a][2]*s2[2] + t2[2];
        o.w = asv[a][3]*s1[3] + t1[3] + asve[a][3]*s2[3] + t2[3];
        *(float4*)&out[(((b*56 + i0 + a)*56 + w) * 512) + ch0] = o;
    }
}

// ---------------------------------------------------------------------------
extern "C" void kernel_launch(void* const* d_in, const int* in_sizes, int n_in,
                              void* d_out, int out_size)
{
    const float* x     = (const float*)d_in[0];
    const float* Wq    = (const float*)d_in[1];
    const float* Wk    = (const float*)d_in[2];
    const float* Wv    = (const float*)d_in[3];
    const float* q_rel = (const float*)d_in[4];
    const float* k_rel = (const float*)d_in[5];
    const float* v_rel = (const float*)d_in[6];
    const float* p_q   = (const float*)d_in[7];
    const float* p_k   = (const float*)d_in[8];
    const float* p_v   = (const float*)d_in[9];
    const float* p_qk  = (const float*)d_in[10];
    const float* p_qr  = (const float*)d_in[11];
    const float* p_kr  = (const float*)d_in[12];
    const float* p_sv  = (const float*)d_in[13];
    const float* p_sve = (const float*)d_in[14];
    float* out = (float*)d_out;

    const int smem_k4 = (3584 + 7104 + 3136) * 4;  // 55296 B
    cudaFuncSetAttribute(qkv_mma_kernel,
                         cudaFuncAttributeMaxDynamicSharedMemorySize, SMEM_MMA);
    cudaFuncSetAttribute(logits_mma_kernel,
                         cudaFuncAttributeMaxDynamicSharedMemorySize, SMEM_LOGITS);
    cudaFuncSetAttribute(attn_out_kernel,
                         cudaFuncAttributeMaxDynamicSharedMemorySize, smem_k4);

    split_w_kernel<<<dim3(32, 16), 256>>>(Wq, Wk, Wv);
    prep_rel_kernel<<<1, 256>>>(q_rel, k_rel);
    qkv_mma_kernel<<<dim3(8, 392), 256, SMEM_MMA>>>(x, p_q, p_k, p_v);
    logits_mma_kernel<<<dim3(896, 8), 128, SMEM_LOGITS>>>(p_qk, p_qr, p_kr);
    softmax_kernel<<<dim3(49, 8, 16), 64>>>();
    attn_out_kernel<<<dim3(896, 8), 256, smem_k4>>>(v_rel, p_sv, p_sve, out);
}

// round 15
// speedup vs baseline: 1.1254x; 1.0517x over previous
#include <cuda_runtime.h>
#include <cuda_bf16.h>
#include <cstdint>

// ---------------------------------------------------------------------------
// AxialAttention (K=56, G=8, CIN=512, COUT=512)
//   k0 : transpose+split W -> g_whi/g_wlo [1024 n][512 k] bf16
//   k1 : qkv GEMM via mma.sync m16n8k16 bf16 (3-product split), inline x split
//   k2 : logits via mma.sync, 8 warps: Qr || Kr concurrent, then QK + combine
//   k3 : in-place softmax over w
//   k4 : attn_out SIMT per (b,w,g)
// ---------------------------------------------------------------------------

#define EPS 1e-3f

__device__ float g_Q[12845056];   // [16][56 w][56 i][256]
__device__ float g_K[12845056];
__device__ float g_V[25690112];   // [16][56 w][56 j][512]
__device__ float g_L[22478848];   // [16][56 w][8 g][3136 ij]
__device__ __align__(16) __nv_bfloat16 g_whi[524288];    // [1024 n][512 k]
__device__ __align__(16) __nv_bfloat16 g_wlo[524288];

__device__ __forceinline__ uint32_t smem_u32(const void* p) {
    uint32_t a;
    asm("{ .reg .u64 t; cvta.to.shared.u64 t, %1; cvt.u32.u64 %0, t; }" : "=r"(a) : "l"(p));
    return a;
}
__device__ __forceinline__ void ldsm4(unsigned* r, uint32_t a) {
    asm volatile("ldmatrix.sync.aligned.m8n8.x4.shared.b16 {%0,%1,%2,%3}, [%4];"
        : "=r"(r[0]), "=r"(r[1]), "=r"(r[2]), "=r"(r[3]) : "r"(a));
}
__device__ __forceinline__ void mma16816(float* d, const unsigned* a, const unsigned* b) {
    asm volatile("mma.sync.aligned.m16n8k16.row.col.f32.bf16.bf16.f32 "
        "{%0,%1,%2,%3}, {%4,%5,%6,%7}, {%8,%9}, {%0,%1,%2,%3};"
        : "+f"(d[0]), "+f"(d[1]), "+f"(d[2]), "+f"(d[3])
        : "r"(a[0]), "r"(a[1]), "r"(a[2]), "r"(a[3]), "r"(b[0]), "r"(b[1]));
}
// smem swizzle: rows of 32 bf16 (64B = 4 chunks of 16B)
__device__ __forceinline__ uint32_t swz(int row, int chunk) {
    return (uint32_t)(row * 64 + ((chunk ^ (row & 3) ^ ((row >> 2) & 1)) << 4));
}
__device__ __forceinline__ void split_pair(float a, float b, unsigned& hi2, unsigned& lo2) {
    __nv_bfloat162 h = __floats2bfloat162_rn(a, b);
    float ra = a - __bfloat162float(h.x);
    float rb = b - __bfloat162float(h.y);
    __nv_bfloat162 l = __floats2bfloat162_rn(ra, rb);
    hi2 = *(unsigned*)&h;
    lo2 = *(unsigned*)&l;
}
__device__ __forceinline__ void split8(float4 a, float4 b, uint4& hi, uint4& lo) {
    split_pair(a.x, a.y, hi.x, lo.x);
    split_pair(a.z, a.w, hi.y, lo.y);
    split_pair(b.x, b.y, hi.z, lo.z);
    split_pair(b.z, b.w, hi.w, lo.w);
}

// ---------------------------------------------------------------------------
// k0: transpose + split W -> g_whi/g_wlo [n][k]
// ---------------------------------------------------------------------------
__global__ __launch_bounds__(256) void split_w_kernel(
    const float* __restrict__ Wq, const float* __restrict__ Wk, const float* __restrict__ Wv)
{
    __shared__ float t[32][33];
    const int n0 = blockIdx.x * 32, k0 = blockIdx.y * 32;
    const float* W; int ncols, col0;
    if (n0 < 256)      { W = Wq; ncols = 256; col0 = n0;       }
    else if (n0 < 512) { W = Wk; ncols = 256; col0 = n0 - 256; }
    else               { W = Wv; ncols = 512; col0 = n0 - 512; }
    const int tx = threadIdx.x & 31, ty = threadIdx.x >> 5;
    #pragma unroll
    for (int i = 0; i < 32; i += 8)
        t[ty + i][tx] = W[(k0 + ty + i) * ncols + col0 + tx];
    __syncthreads();
    #pragma unroll
    for (int i = 0; i < 32; i += 8) {
        const float v = t[tx][ty + i];
        const __nv_bfloat16 h = __float2bfloat16_rn(v);
        g_whi[(n0 + ty + i) * 512 + k0 + tx] = h;
        g_wlo[(n0 + ty + i) * 512 + k0 + tx] = __float2bfloat16_rn(v - __bfloat162float(h));
    }
}

// ---------------------------------------------------------------------------
// k1: mma.sync bf16 QKV GEMM. BM=128 BN=128 BK=32, 256 thr (8 warps, 4Mx2N)
// ---------------------------------------------------------------------------
#define STG 32768
#define SMEM_MMA (2*STG + 1024)

__global__ __launch_bounds__(256, 1) void qkv_mma_kernel(
    const float* __restrict__ x,
    const float* __restrict__ pq, const float* __restrict__ pk, const float* __restrict__ pv)
{
    extern __shared__ char smem[];
    float* Ssc = (float*)(smem + 2*STG);
    float* Tsc = Ssc + 128;

    const int tid  = threadIdx.x;
    const int lane = tid & 31, wid = tid >> 5;
    const int mbase = (wid >> 1) * 32;
    const int nbase = (wid & 1) * 64;
    const int n0 = blockIdx.x * 128;
    const int m0 = blockIdx.y * 128;
    const uint32_t sb = smem_u32(smem);

    const float* P; float* dst; int ncols, colbase;
    if (n0 < 256)      { P = pq; dst = g_Q; ncols = 256; colbase = n0;       }
    else if (n0 < 512) { P = pk; dst = g_K; ncols = 256; colbase = n0 - 256; }
    else               { P = pv; dst = g_V; ncols = 512; colbase = n0 - 512; }

    if (tid < 128) {
        const int ch = colbase + tid;
        const float s = P[ch] * rsqrtf(P[3*ncols + ch] + EPS);
        Ssc[tid] = s;
        Tsc[tid] = P[ncols + ch] - P[2*ncols + ch] * s;
    }

    const int prow = tid >> 1;
    const int pc   = (tid & 1) * 2;
    const size_t aoff = (size_t)(m0 + prow) * 512;
    const size_t boff = (size_t)(n0 + prow) * 512;
    const uint32_t so0 = swz(prow, pc), so1 = swz(prow, pc + 1);

    float acc[2][8][4];
    #pragma unroll
    for (int mt = 0; mt < 2; mt++)
        #pragma unroll
        for (int nt = 0; nt < 8; nt++)
            #pragma unroll
            for (int c = 0; c < 4; c++) acc[mt][nt][c] = 0.f;

    {
        const int koff = pc * 8;
        const float4* px = (const float4*)(x + aoff + koff);
        float4 x0 = px[0], x1 = px[1], x2 = px[2], x3 = px[3];
        uint4 h0, l0, h1, l1;
        split8(x0, x1, h0, l0);
        split8(x2, x3, h1, l1);
        const uint4* pwh = (const uint4*)(g_whi + boff + koff);
        const uint4* pwl = (const uint4*)(g_wlo + boff + koff);
        char* s = smem;
        *(uint4*)(s + so0)          = h0; *(uint4*)(s + so1)          = h1;
        *(uint4*)(s + 8192  + so0)  = l0; *(uint4*)(s + 8192  + so1)  = l1;
        *(uint4*)(s + 16384 + so0)  = pwh[0]; *(uint4*)(s + 16384 + so1) = pwh[1];
        *(uint4*)(s + 24576 + so0)  = pwl[0]; *(uint4*)(s + 24576 + so1) = pwl[1];
    }
    __syncthreads();

    for (int ks = 0; ks < 16; ks++) {
        const int cur = ks & 1;
        float4 fx[4]; uint4 fw[4];
        if (ks < 15) {
            const int koff = (ks + 1) * 32 + pc * 8;
            const float4* px = (const float4*)(x + aoff + koff);
            fx[0] = px[0]; fx[1] = px[1]; fx[2] = px[2]; fx[3] = px[3];
            const uint4* pwh = (const uint4*)(g_whi + boff + koff);
            const uint4* pwl = (const uint4*)(g_wlo + boff + koff);
            fw[0] = pwh[0]; fw[1] = pwh[1];
            fw[2] = pwl[0]; fw[3] = pwl[1];
        }
        const uint32_t stb = sb + cur * STG;
        #pragma unroll
        for (int kst = 0; kst < 2; kst++) {
            unsigned ah[2][4], al[2][4], bh[16], bl[16];
            #pragma unroll
            for (int mt = 0; mt < 2; mt++) {
                const int row = mbase + mt*16 + (lane & 15);
                const int ch  = kst*2 + (lane >> 4);
                const uint32_t ad = stb + swz(row, ch);
                ldsm4(ah[mt], ad);
                ldsm4(al[mt], ad + 8192);
            }
            #pragma unroll
            for (int p = 0; p < 4; p++) {
                const int row = nbase + (2*p + (lane >> 4)) * 8 + (lane & 7);
                const int ch  = kst*2 + ((lane >> 3) & 1);
                const uint32_t bd = stb + 16384 + swz(row, ch);
                ldsm4(&bh[p*4], bd);
                ldsm4(&bl[p*4], bd + 8192);
            }
            #pragma unroll
            for (int mt = 0; mt < 2; mt++)
                #pragma unroll
                for (int nt = 0; nt < 8; nt++) {
                    mma16816(acc[mt][nt], ah[mt], &bh[nt*2]);
                    mma16816(acc[mt][nt], al[mt], &bh[nt*2]);
                    mma16816(acc[mt][nt], ah[mt], &bl[nt*2]);
                }
        }
        __syncthreads();
        if (ks < 15) {
            uint4 h0, l0, h1, l1;
            split8(fx[0], fx[1], h0, l0);
            split8(fx[2], fx[3], h1, l1);
            char* s = smem + (cur ^ 1) * STG;
            *(uint4*)(s + so0)         = h0;    *(uint4*)(s + so1)         = h1;
            *(uint4*)(s + 8192  + so0) = l0;    *(uint4*)(s + 8192  + so1) = l1;
            *(uint4*)(s + 16384 + so0) = fw[0]; *(uint4*)(s + 16384 + so1) = fw[1];
            *(uint4*)(s + 24576 + so0) = fw[2]; *(uint4*)(s + 24576 + so1) = fw[3];
            __syncthreads();
        }
    }

    #pragma unroll
    for (int mt = 0; mt < 2; mt++) {
        #pragma unroll
        for (int half = 0; half < 2; half++) {
            const int m = m0 + mbase + mt*16 + (lane >> 2) + half*8;
            const int b = m / 3136;
            const int rem = m - b*3136;
            const int i = rem / 56;
            const int w = rem - i*56;
            float* dr = dst + (size_t)((b*56 + w)*56 + i) * ncols + colbase;
            #pragma unroll
            for (int nt = 0; nt < 8; nt++) {
                const int col = nbase + nt*8 + (lane & 3)*2;
                float2 o;
                o.x = acc[mt][nt][half*2+0] * Ssc[col]   + Tsc[col];
                o.y = acc[mt][nt][half*2+1] * Ssc[col+1] + Tsc[col+1];
                *(float2*)(dr + col) = o;
            }
        }
    }
}

// ---------------------------------------------------------------------------
// k2: logits via mma.sync. One block per (b,w,g), 256 threads (8 warps):
//   phase 1: warps 0-3 compute Qr_full, warps 4-7 compute Kr_full (parallel)
//   phase 2: warps 4-7 compute QK + diagonal-gather combine + store
// ---------------------------------------------------------------------------
#define OFF_QHI  0
#define OFF_QLO  4096
#define OFF_KHI  8192
#define OFF_KLO  12288
#define OFF_RQHI 16384
#define OFF_RQLO 23552
#define OFF_RKHI 30720
#define OFF_RKLO 37888
#define OFF_QRS  45056
#define OFF_KRS  74240
#define SMEM_LOGITS 103424

__global__ __launch_bounds__(256) void logits_mma_kernel(
    const float* __restrict__ q_rel, const float* __restrict__ k_rel,
    const float* __restrict__ pqk, const float* __restrict__ pqr, const float* __restrict__ pkr)
{
    extern __shared__ char sm[];
    const uint32_t sb = smem_u32(sm);
    const int tid = threadIdx.x;
    const int lane = tid & 31, wid = tid >> 5;
    const int bw = blockIdx.x;
    const int g  = blockIdx.y;

    // --- convert Q, K group slices (56 rows x 32 ch) to bf16 hi/lo, swizzled
    const float* qbase = g_Q + (size_t)bw * 56 * 256 + g * 32;
    const float* kbase = g_K + (size_t)bw * 56 * 256 + g * 32;
    for (int t = tid; t < 224; t += 256) {
        const int row = t >> 2, ch = t & 3;
        const uint32_t o = swz(row, ch);
        float4 a = *(const float4*)(qbase + row*256 + ch*8);
        float4 b = *(const float4*)(qbase + row*256 + ch*8 + 4);
        uint4 hi, lo; split8(a, b, hi, lo);
        *(uint4*)(sm + OFF_QHI + o) = hi;
        *(uint4*)(sm + OFF_QLO + o) = lo;
        a = *(const float4*)(kbase + row*256 + ch*8);
        b = *(const float4*)(kbase + row*256 + ch*8 + 4);
        split8(a, b, hi, lo);
        *(uint4*)(sm + OFF_KHI + o) = hi;
        *(uint4*)(sm + OFF_KLO + o) = lo;
    }
    // --- convert rel tables (111 rows x 32)
    for (int t = tid; t < 444; t += 256) {
        const int row = t >> 2, ch = t & 3;
        const uint32_t o = swz(row, ch);
        float4 a = *(const float4*)(q_rel + row*32 + ch*8);
        float4 b = *(const float4*)(q_rel + row*32 + ch*8 + 4);
        uint4 hi, lo; split8(a, b, hi, lo);
        *(uint4*)(sm + OFF_RQHI + o) = hi;
        *(uint4*)(sm + OFF_RQLO + o) = lo;
        a = *(const float4*)(k_rel + row*32 + ch*8);
        b = *(const float4*)(k_rel + row*32 + ch*8 + 4);
        split8(a, b, hi, lo);
        *(uint4*)(sm + OFF_RKHI + o) = hi;
        *(uint4*)(sm + OFF_RKLO + o) = lo;
    }
    __syncthreads();

    float* qrs = (float*)(sm + OFF_QRS);
    float* krs = (float*)(sm + OFF_KRS);
    const int fr = lane >> 2, fc = (lane & 3) * 2;

    // --- phase 1: warps 0-3 -> Qr_full, warps 4-7 -> Kr_full  (parallel)
    {
        const bool isQ = (wid < 4);
        const int mrow0 = (isQ ? wid : (wid - 4)) * 16;
        const uint32_t ahi = isQ ? (sb + OFF_QHI)  : (sb + OFF_KHI);
        const uint32_t alo = isQ ? (sb + OFF_QLO)  : (sb + OFF_KLO);
        const uint32_t bhi = isQ ? (sb + OFF_RQHI) : (sb + OFF_RKHI);
        const uint32_t blo = isQ ? (sb + OFF_RQLO) : (sb + OFF_RKLO);
        float* outp = isQ ? qrs : krs;

        unsigned ah[2][4], al[2][4];
        #pragma unroll
        for (int kst = 0; kst < 2; kst++) {
            const int row = mrow0 + (lane & 15);
            const int ch  = kst*2 + (lane >> 4);
            ldsm4(ah[kst], ahi + swz(row, ch));
            ldsm4(al[kst], alo + swz(row, ch));
        }
        float acc[14][4];
        #pragma unroll
        for (int nt = 0; nt < 14; nt++)
            #pragma unroll
            for (int c = 0; c < 4; c++) acc[nt][c] = 0.f;
        #pragma unroll
        for (int kst = 0; kst < 2; kst++)
            #pragma unroll
            for (int p = 0; p < 7; p++) {
                unsigned bh[4], bl[4];
                const int brow = (2*p + (lane >> 4)) * 8 + (lane & 7);
                const int bch  = kst*2 + ((lane >> 3) & 1);
                ldsm4(bh, bhi + swz(brow, bch));
                ldsm4(bl, blo + swz(brow, bch));
                #pragma unroll
                for (int t2 = 0; t2 < 2; t2++) {
                    mma16816(acc[2*p+t2], ah[kst], &bh[2*t2]);
                    mma16816(acc[2*p+t2], al[kst], &bh[2*t2]);
                    mma16816(acc[2*p+t2], ah[kst], &bl[2*t2]);
                }
            }
        #pragma unroll
        for (int nt = 0; nt < 14; nt++) {
            *(float2*)&outp[(mrow0+fr)*114   + nt*8 + fc] = make_float2(acc[nt][0], acc[nt][1]);
            *(float2*)&outp[(mrow0+fr+8)*114 + nt*8 + fc] = make_float2(acc[nt][2], acc[nt][3]);
        }
    }
    __syncthreads();

    // --- phase 2: warps 4-7 compute QK and combine
    if (wid >= 4) {
        const int mrow0 = (wid - 4) * 16;
        const float sqk = pqk[g] * rsqrtf(pqk[24+g] + EPS);
        const float sqr = pqr[g] * rsqrtf(pqr[24+g] + EPS);
        const float skr = pkr[g] * rsqrtf(pkr[24+g] + EPS);
        const float tsum = (pqk[8+g] - pqk[16+g]*sqk)
                         + (pqr[8+g] - pqr[16+g]*sqr)
                         + (pkr[8+g] - pkr[16+g]*skr);

        float qk[8][4];
        #pragma unroll
        for (int nt = 0; nt < 8; nt++)
            #pragma unroll
            for (int c = 0; c < 4; c++) qk[nt][c] = 0.f;
        unsigned ah[2][4], al[2][4];
        #pragma unroll
        for (int kst = 0; kst < 2; kst++) {
            const int row = mrow0 + (lane & 15);
            const int ch  = kst*2 + (lane >> 4);
            ldsm4(ah[kst], sb + OFF_QHI + swz(row, ch));
            ldsm4(al[kst], sb + OFF_QLO + swz(row, ch));
        }
        #pragma unroll
        for (int kst = 0; kst < 2; kst++)
            #pragma unroll
            for (int p = 0; p < 4; p++) {
                unsigned bh[4], bl[4];
                const int brow = (2*p + (lane >> 4)) * 8 + (lane & 7);
                const int bch  = kst*2 + ((lane >> 3) & 1);
                ldsm4(bh, sb + OFF_KHI + swz(brow, bch));
                ldsm4(bl, sb + OFF_KLO + swz(brow, bch));
                #pragma unroll
                for (int t2 = 0; t2 < 2; t2++) {
                    mma16816(qk[2*p+t2], ah[kst], &bh[2*t2]);
                    mma16816(qk[2*p+t2], al[kst], &bh[2*t2]);
                    mma16816(qk[2*p+t2], ah[kst], &bl[2*t2]);
                }
            }

        float* Lp = g_L + ((size_t)bw*8 + g)*3136;
        #pragma unroll
        for (int nt = 0; nt < 7; nt++) {
            const int j0 = nt*8 + fc;
            #pragma unroll
            for (int half = 0; half < 2; half++) {
                const int i = mrow0 + fr + half*8;
                if (i < 56) {
                    const int dq = 55 + i - j0;
                    float2 o;
                    o.x = sqk*qk[nt][half*2+0] + sqr*qrs[i*114 + dq]
                        + skr*krs[j0*114 + 55 + j0 - i] + tsum;
                    o.y = sqk*qk[nt][half*2+1] + sqr*qrs[i*114 + dq - 1]
                        + skr*krs[(j0+1)*114 + 56 + j0 - i] + tsum;
                    *(float2*)&Lp[i*56 + j0] = o;
                }
            }
        }
    }
}

// ---------------------------------------------------------------------------
// k3: softmax over w (axis=-2), in place
// ---------------------------------------------------------------------------
__global__ __launch_bounds__(64) void softmax_kernel()
{
    const int t  = threadIdx.x;
    const int ij = blockIdx.x * 64 + t;
    const int g  = blockIdx.y;
    const int b  = blockIdx.z;
    float* base = g_L + ((size_t)b*448 + g)*3136 + ij;
    const int ws = 8*3136;

    float v[56];
    float mx = -3.4e38f;
    #pragma unroll
    for (int w = 0; w < 56; w++) { v[w] = base[w*ws]; mx = fmaxf(mx, v[w]); }
    float s = 0.f;
    #pragma unroll
    for (int w = 0; w < 56; w++) { v[w] = __expf(v[w] - mx); s += v[w]; }
    const float inv = 1.f / s;
    #pragma unroll
    for (int w = 0; w < 56; w++) base[w*ws] = v[w] * inv;
}

// ---------------------------------------------------------------------------
// k4: attention output per (b,w,g) — SIMT (measured fastest)
// ---------------------------------------------------------------------------
__global__ __launch_bounds__(256) void attn_out_kernel(
    const float* __restrict__ v_rel,
    const float* __restrict__ psv, const float* __restrict__ psve,
    float* __restrict__ out)
{
    extern __shared__ float smf[];
    float* Vg     = smf;              // [56][64]
    float* vrel_s = smf + 3584;       // [111][64]
    float* sim_s  = smf + 10688;      // [56][56]

    const int tid = threadIdx.x;
    const int bw  = blockIdx.x;
    const int g   = blockIdx.y;
    const int b   = bw / 56, w = bw - b*56;

    const float* vsrc = g_V + (size_t)bw * (56*512) + g*64;
    for (int idx = tid; idx < 3584; idx += 256) {
        const int j = idx >> 6, c = idx & 63;
        Vg[idx] = vsrc[j*512 + c];
    }
    for (int idx = tid; idx < 7104; idx += 256) vrel_s[idx] = v_rel[idx];
    const float* simsrc = g_L + ((size_t)bw*8 + g)*3136;
    for (int idx = tid; idx < 3136; idx += 256) sim_s[idx] = simsrc[idx];
    __syncthreads();

    if (tid >= 224) return;
    const int ti = tid >> 4, tc = tid & 15;
    const int i0 = ti*4, c0 = tc*4;
    const int ch0 = g*64 + c0;

    float asv[4][4], asve[4][4];
    #pragma unroll
    for (int a = 0; a < 4; a++)
        #pragma unroll
        for (int c = 0; c < 4; c++) { asv[a][c]=0.f; asve[a][c]=0.f; }

    #pragma unroll 4
    for (int j = 0; j < 56; j++) {
        const float4 vv = *(const float4*)&Vg[j*64 + c0];
        #pragma unroll
        for (int a = 0; a < 4; a++) {
            const float s = sim_s[(i0+a)*56 + j];
            asv[a][0] = fmaf(s, vv.x, asv[a][0]);
            asv[a][1] = fmaf(s, vv.y, asv[a][1]);
            asv[a][2] = fmaf(s, vv.z, asv[a][2]);
            asv[a][3] = fmaf(s, vv.w, asv[a][3]);
        }
    }
    for (int d = 52 - i0; d <= 110 - i0; d++) {
        const float4 vr = *(const float4*)&vrel_s[d*64 + c0];
        #pragma unroll
        for (int a = 0; a < 4; a++) {
            const int j = i0 + a + d - 55;
            if ((unsigned)j < 56u) {
                const float s = sim_s[(i0+a)*56 + j];
                asve[a][0] = fmaf(s, vr.x, asve[a][0]);
                asve[a][1] = fmaf(s, vr.y, asve[a][1]);
                asve[a][2] = fmaf(s, vr.z, asve[a][2]);
                asve[a][3] = fmaf(s, vr.w, asve[a][3]);
            }
        }
    }

    float s1[4], t1[4], s2[4], t2[4];
    #pragma unroll
    for (int cc = 0; cc < 4; cc++) {
        const int ch = ch0 + cc;
        const float a1 = psv[ch] * rsqrtf(psv[1536+ch] + EPS);
        s1[cc] = a1; t1[cc] = psv[512+ch] - psv[1024+ch]*a1;
        const float a2 = psve[ch] * rsqrtf(psve[1536+ch] + EPS);
        s2[cc] = a2; t2[cc] = psve[512+ch] - psve[1024+ch]*a2;
    }
    #pragma unroll
    for (int a = 0; a < 4; a++) {
        float4 o;
        o.x = asv[a][0]*s1[0] + t1[0] + asve[a][0]*s2[0] + t2[0];
        o.y = asv[a][1]*s1[1] + t1[1] + asve[a][1]*s2[1] + t2[1];
        o.z = asv[a][2]*s1[2] + t1[2] + asve[a][2]*s2[2] + t2[2];
        o.w = asv[a][3]*s1[3] + t1[3] + asve[a][3]*s2[3] + t2[3];
        *(float4*)&out[(((b*56 + i0 + a)*56 + w) * 512) + ch0] = o;
    }
}

// ---------------------------------------------------------------------------
extern "C" void kernel_launch(void* const* d_in, const int* in_sizes, int n_in,
                              void* d_out, int out_size)
{
    const float* x     = (const float*)d_in[0];
    const float* Wq    = (const float*)d_in[1];
    const float* Wk    = (const float*)d_in[2];
    const float* Wv    = (const float*)d_in[3];
    const float* q_rel = (const float*)d_in[4];
    const float* k_rel = (const float*)d_in[5];
    const float* v_rel = (const float*)d_in[6];
    const float* p_q   = (const float*)d_in[7];
    const float* p_k   = (const float*)d_in[8];
    const float* p_v   = (const float*)d_in[9];
    const float* p_qk  = (const float*)d_in[10];
    const float* p_qr  = (const float*)d_in[11];
    const float* p_kr  = (const float*)d_in[12];
    const float* p_sv  = (const float*)d_in[13];
    const float* p_sve = (const float*)d_in[14];
    float* out = (float*)d_out;

    const int smem_k4 = (3584 + 7104 + 3136) * 4;  // 55296 B
    cudaFuncSetAttribute(qkv_mma_kernel,
                         cudaFuncAttributeMaxDynamicSharedMemorySize, SMEM_MMA);
    cudaFuncSetAttribute(logits_mma_kernel,
                         cudaFuncAttributeMaxDynamicSharedMemorySize, SMEM_LOGITS);
    cudaFuncSetAttribute(attn_out_kernel,
                         cudaFuncAttributeMaxDynamicSharedMemorySize, smem_k4);

    split_w_kernel<<<dim3(32, 16), 256>>>(Wq, Wk, Wv);
    qkv_mma_kernel<<<dim3(8, 392), 256, SMEM_MMA>>>(x, p_q, p_k, p_v);
    logits_mma_kernel<<<dim3(896, 8), 256, SMEM_LOGITS>>>(q_rel, k_rel, p_qk, p_qr, p_kr);
    softmax_kernel<<<dim3(49, 8, 16), 64>>>();
    attn_out_kernel<<<dim3(896, 8), 256, smem_k4>>>(v_rel, p_sv, p_sve, out);
}

// round 16
// speedup vs baseline: 1.1801x; 1.0486x over previous
#include <cuda_runtime.h>
#include <cuda_bf16.h>
#include <cstdint>

// ---------------------------------------------------------------------------
// AxialAttention (K=56, G=8, CIN=512, COUT=512)
//   k0 : transpose+split W -> g_whi/g_wlo [1024 n][512 k] bf16
//   k1 : qkv GEMM via mma.sync m16n8k16 bf16 (3-product split), inline x split
//   k2 : logits via mma.sync, 8 warps: Qr || Kr concurrent, then QK + combine
//   k3 : in-place softmax over w
//   k4 : attn_out SIMT per (b,w,g); vrel read from L2 (no smem staging)
// ---------------------------------------------------------------------------

#define EPS 1e-3f

__device__ float g_Q[12845056];   // [16][56 w][56 i][256]
__device__ float g_K[12845056];
__device__ float g_V[25690112];   // [16][56 w][56 j][512]
__device__ float g_L[22478848];   // [16][56 w][8 g][3136 ij]
__device__ __align__(16) __nv_bfloat16 g_whi[524288];    // [1024 n][512 k]
__device__ __align__(16) __nv_bfloat16 g_wlo[524288];

__device__ __forceinline__ uint32_t smem_u32(const void* p) {
    uint32_t a;
    asm("{ .reg .u64 t; cvta.to.shared.u64 t, %1; cvt.u32.u64 %0, t; }" : "=r"(a) : "l"(p));
    return a;
}
__device__ __forceinline__ void ldsm4(unsigned* r, uint32_t a) {
    asm volatile("ldmatrix.sync.aligned.m8n8.x4.shared.b16 {%0,%1,%2,%3}, [%4];"
        : "=r"(r[0]), "=r"(r[1]), "=r"(r[2]), "=r"(r[3]) : "r"(a));
}
__device__ __forceinline__ void mma16816(float* d, const unsigned* a, const unsigned* b) {
    asm volatile("mma.sync.aligned.m16n8k16.row.col.f32.bf16.bf16.f32 "
        "{%0,%1,%2,%3}, {%4,%5,%6,%7}, {%8,%9}, {%0,%1,%2,%3};"
        : "+f"(d[0]), "+f"(d[1]), "+f"(d[2]), "+f"(d[3])
        : "r"(a[0]), "r"(a[1]), "r"(a[2]), "r"(a[3]), "r"(b[0]), "r"(b[1]));
}
// smem swizzle: rows of 32 bf16 (64B = 4 chunks of 16B)
__device__ __forceinline__ uint32_t swz(int row, int chunk) {
    return (uint32_t)(row * 64 + ((chunk ^ (row & 3) ^ ((row >> 2) & 1)) << 4));
}
__device__ __forceinline__ void split_pair(float a, float b, unsigned& hi2, unsigned& lo2) {
    __nv_bfloat162 h = __floats2bfloat162_rn(a, b);
    float ra = a - __bfloat162float(h.x);
    float rb = b - __bfloat162float(h.y);
    __nv_bfloat162 l = __floats2bfloat162_rn(ra, rb);
    hi2 = *(unsigned*)&h;
    lo2 = *(unsigned*)&l;
}
__device__ __forceinline__ void split8(float4 a, float4 b, uint4& hi, uint4& lo) {
    split_pair(a.x, a.y, hi.x, lo.x);
    split_pair(a.z, a.w, hi.y, lo.y);
    split_pair(b.x, b.y, hi.z, lo.z);
    split_pair(b.z, b.w, hi.w, lo.w);
}

// ---------------------------------------------------------------------------
// k0: transpose + split W -> g_whi/g_wlo [n][k]
// ---------------------------------------------------------------------------
__global__ __launch_bounds__(256) void split_w_kernel(
    const float* __restrict__ Wq, const float* __restrict__ Wk, const float* __restrict__ Wv)
{
    __shared__ float t[32][33];
    const int n0 = blockIdx.x * 32, k0 = blockIdx.y * 32;
    const float* W; int ncols, col0;
    if (n0 < 256)      { W = Wq; ncols = 256; col0 = n0;       }
    else if (n0 < 512) { W = Wk; ncols = 256; col0 = n0 - 256; }
    else               { W = Wv; ncols = 512; col0 = n0 - 512; }
    const int tx = threadIdx.x & 31, ty = threadIdx.x >> 5;
    #pragma unroll
    for (int i = 0; i < 32; i += 8)
        t[ty + i][tx] = W[(k0 + ty + i) * ncols + col0 + tx];
    __syncthreads();
    #pragma unroll
    for (int i = 0; i < 32; i += 8) {
        const float v = t[tx][ty + i];
        const __nv_bfloat16 h = __float2bfloat16_rn(v);
        g_whi[(n0 + ty + i) * 512 + k0 + tx] = h;
        g_wlo[(n0 + ty + i) * 512 + k0 + tx] = __float2bfloat16_rn(v - __bfloat162float(h));
    }
}

// ---------------------------------------------------------------------------
// k1: mma.sync bf16 QKV GEMM. BM=128 BN=128 BK=32, 256 thr (8 warps, 4Mx2N)
// ---------------------------------------------------------------------------
#define STG 32768
#define SMEM_MMA (2*STG + 1024)

__global__ __launch_bounds__(256, 1) void qkv_mma_kernel(
    const float* __restrict__ x,
    const float* __restrict__ pq, const float* __restrict__ pk, const float* __restrict__ pv)
{
    extern __shared__ char smem[];
    float* Ssc = (float*)(smem + 2*STG);
    float* Tsc = Ssc + 128;

    const int tid  = threadIdx.x;
    const int lane = tid & 31, wid = tid >> 5;
    const int mbase = (wid >> 1) * 32;
    const int nbase = (wid & 1) * 64;
    const int n0 = blockIdx.x * 128;
    const int m0 = blockIdx.y * 128;
    const uint32_t sb = smem_u32(smem);

    const float* P; float* dst; int ncols, colbase;
    if (n0 < 256)      { P = pq; dst = g_Q; ncols = 256; colbase = n0;       }
    else if (n0 < 512) { P = pk; dst = g_K; ncols = 256; colbase = n0 - 256; }
    else               { P = pv; dst = g_V; ncols = 512; colbase = n0 - 512; }

    if (tid < 128) {
        const int ch = colbase + tid;
        const float s = P[ch] * rsqrtf(P[3*ncols + ch] + EPS);
        Ssc[tid] = s;
        Tsc[tid] = P[ncols + ch] - P[2*ncols + ch] * s;
    }

    const int prow = tid >> 1;
    const int pc   = (tid & 1) * 2;
    const size_t aoff = (size_t)(m0 + prow) * 512;
    const size_t boff = (size_t)(n0 + prow) * 512;
    const uint32_t so0 = swz(prow, pc), so1 = swz(prow, pc + 1);

    float acc[2][8][4];
    #pragma unroll
    for (int mt = 0; mt < 2; mt++)
        #pragma unroll
        for (int nt = 0; nt < 8; nt++)
            #pragma unroll
            for (int c = 0; c < 4; c++) acc[mt][nt][c] = 0.f;

    {
        const int koff = pc * 8;
        const float4* px = (const float4*)(x + aoff + koff);
        float4 x0 = px[0], x1 = px[1], x2 = px[2], x3 = px[3];
        uint4 h0, l0, h1, l1;
        split8(x0, x1, h0, l0);
        split8(x2, x3, h1, l1);
        const uint4* pwh = (const uint4*)(g_whi + boff + koff);
        const uint4* pwl = (const uint4*)(g_wlo + boff + koff);
        char* s = smem;
        *(uint4*)(s + so0)          = h0; *(uint4*)(s + so1)          = h1;
        *(uint4*)(s + 8192  + so0)  = l0; *(uint4*)(s + 8192  + so1)  = l1;
        *(uint4*)(s + 16384 + so0)  = pwh[0]; *(uint4*)(s + 16384 + so1) = pwh[1];
        *(uint4*)(s + 24576 + so0)  = pwl[0]; *(uint4*)(s + 24576 + so1) = pwl[1];
    }
    __syncthreads();

    for (int ks = 0; ks < 16; ks++) {
        const int cur = ks & 1;
        float4 fx[4]; uint4 fw[4];
        if (ks < 15) {
            const int koff = (ks + 1) * 32 + pc * 8;
            const float4* px = (const float4*)(x + aoff + koff);
            fx[0] = px[0]; fx[1] = px[1]; fx[2] = px[2]; fx[3] = px[3];
            const uint4* pwh = (const uint4*)(g_whi + boff + koff);
            const uint4* pwl = (const uint4*)(g_wlo + boff + koff);
            fw[0] = pwh[0]; fw[1] = pwh[1];
            fw[2] = pwl[0]; fw[3] = pwl[1];
        }
        const uint32_t stb = sb + cur * STG;
        #pragma unroll
        for (int kst = 0; kst < 2; kst++) {
            unsigned ah[2][4], al[2][4], bh[16], bl[16];
            #pragma unroll
            for (int mt = 0; mt < 2; mt++) {
                const int row = mbase + mt*16 + (lane & 15);
                const int ch  = kst*2 + (lane >> 4);
                const uint32_t ad = stb + swz(row, ch);
                ldsm4(ah[mt], ad);
                ldsm4(al[mt], ad + 8192);
            }
            #pragma unroll
            for (int p = 0; p < 4; p++) {
                const int row = nbase + (2*p + (lane >> 4)) * 8 + (lane & 7);
                const int ch  = kst*2 + ((lane >> 3) & 1);
                const uint32_t bd = stb + 16384 + swz(row, ch);
                ldsm4(&bh[p*4], bd);
                ldsm4(&bl[p*4], bd + 8192);
            }
            #pragma unroll
            for (int mt = 0; mt < 2; mt++)
                #pragma unroll
                for (int nt = 0; nt < 8; nt++) {
                    mma16816(acc[mt][nt], ah[mt], &bh[nt*2]);
                    mma16816(acc[mt][nt], al[mt], &bh[nt*2]);
                    mma16816(acc[mt][nt], ah[mt], &bl[nt*2]);
                }
        }
        __syncthreads();
        if (ks < 15) {
            uint4 h0, l0, h1, l1;
            split8(fx[0], fx[1], h0, l0);
            split8(fx[2], fx[3], h1, l1);
            char* s = smem + (cur ^ 1) * STG;
            *(uint4*)(s + so0)         = h0;    *(uint4*)(s + so1)         = h1;
            *(uint4*)(s + 8192  + so0) = l0;    *(uint4*)(s + 8192  + so1) = l1;
            *(uint4*)(s + 16384 + so0) = fw[0]; *(uint4*)(s + 16384 + so1) = fw[1];
            *(uint4*)(s + 24576 + so0) = fw[2]; *(uint4*)(s + 24576 + so1) = fw[3];
            __syncthreads();
        }
    }

    #pragma unroll
    for (int mt = 0; mt < 2; mt++) {
        #pragma unroll
        for (int half = 0; half < 2; half++) {
            const int m = m0 + mbase + mt*16 + (lane >> 2) + half*8;
            const int b = m / 3136;
            const int rem = m - b*3136;
            const int i = rem / 56;
            const int w = rem - i*56;
            float* dr = dst + (size_t)((b*56 + w)*56 + i) * ncols + colbase;
            #pragma unroll
            for (int nt = 0; nt < 8; nt++) {
                const int col = nbase + nt*8 + (lane & 3)*2;
                float2 o;
                o.x = acc[mt][nt][half*2+0] * Ssc[col]   + Tsc[col];
                o.y = acc[mt][nt][half*2+1] * Ssc[col+1] + Tsc[col+1];
                *(float2*)(dr + col) = o;
            }
        }
    }
}

// ---------------------------------------------------------------------------
// k2: logits via mma.sync. One block per (b,w,g), 256 threads (8 warps):
//   phase 1: warps 0-3 compute Qr_full, warps 4-7 compute Kr_full (parallel)
//   phase 2: warps 4-7 compute QK + diagonal-gather combine + store
// ---------------------------------------------------------------------------
#define OFF_QHI  0
#define OFF_QLO  4096
#define OFF_KHI  8192
#define OFF_KLO  12288
#define OFF_RQHI 16384
#define OFF_RQLO 23552
#define OFF_RKHI 30720
#define OFF_RKLO 37888
#define OFF_QRS  45056
#define OFF_KRS  74240
#define SMEM_LOGITS 103424

__global__ __launch_bounds__(256) void logits_mma_kernel(
    const float* __restrict__ q_rel, const float* __restrict__ k_rel,
    const float* __restrict__ pqk, const float* __restrict__ pqr, const float* __restrict__ pkr)
{
    extern __shared__ char sm[];
    const uint32_t sb = smem_u32(sm);
    const int tid = threadIdx.x;
    const int lane = tid & 31, wid = tid >> 5;
    const int bw = blockIdx.x;
    const int g  = blockIdx.y;

    const float* qbase = g_Q + (size_t)bw * 56 * 256 + g * 32;
    const float* kbase = g_K + (size_t)bw * 56 * 256 + g * 32;
    for (int t = tid; t < 224; t += 256) {
        const int row = t >> 2, ch = t & 3;
        const uint32_t o = swz(row, ch);
        float4 a = *(const float4*)(qbase + row*256 + ch*8);
        float4 b = *(const float4*)(qbase + row*256 + ch*8 + 4);
        uint4 hi, lo; split8(a, b, hi, lo);
        *(uint4*)(sm + OFF_QHI + o) = hi;
        *(uint4*)(sm + OFF_QLO + o) = lo;
        a = *(const float4*)(kbase + row*256 + ch*8);
        b = *(const float4*)(kbase + row*256 + ch*8 + 4);
        split8(a, b, hi, lo);
        *(uint4*)(sm + OFF_KHI + o) = hi;
        *(uint4*)(sm + OFF_KLO + o) = lo;
    }
    for (int t = tid; t < 444; t += 256) {
        const int row = t >> 2, ch = t & 3;
        const uint32_t o = swz(row, ch);
        float4 a = *(const float4*)(q_rel + row*32 + ch*8);
        float4 b = *(const float4*)(q_rel + row*32 + ch*8 + 4);
        uint4 hi, lo; split8(a, b, hi, lo);
        *(uint4*)(sm + OFF_RQHI + o) = hi;
        *(uint4*)(sm + OFF_RQLO + o) = lo;
        a = *(const float4*)(k_rel + row*32 + ch*8);
        b = *(const float4*)(k_rel + row*32 + ch*8 + 4);
        split8(a, b, hi, lo);
        *(uint4*)(sm + OFF_RKHI + o) = hi;
        *(uint4*)(sm + OFF_RKLO + o) = lo;
    }
    __syncthreads();

    float* qrs = (float*)(sm + OFF_QRS);
    float* krs = (float*)(sm + OFF_KRS);
    const int fr = lane >> 2, fc = (lane & 3) * 2;

    {
        const bool isQ = (wid < 4);
        const int mrow0 = (isQ ? wid : (wid - 4)) * 16;
        const uint32_t ahi = isQ ? (sb + OFF_QHI)  : (sb + OFF_KHI);
        const uint32_t alo = isQ ? (sb + OFF_QLO)  : (sb + OFF_KLO);
        const uint32_t bhi = isQ ? (sb + OFF_RQHI) : (sb + OFF_RKHI);
        const uint32_t blo = isQ ? (sb + OFF_RQLO) : (sb + OFF_RKLO);
        float* outp = isQ ? qrs : krs;

        unsigned ah[2][4], al[2][4];
        #pragma unroll
        for (int kst = 0; kst < 2; kst++) {
            const int row = mrow0 + (lane & 15);
            const int ch  = kst*2 + (lane >> 4);
            ldsm4(ah[kst], ahi + swz(row, ch));
            ldsm4(al[kst], alo + swz(row, ch));
        }
        float acc[14][4];
        #pragma unroll
        for (int nt = 0; nt < 14; nt++)
            #pragma unroll
            for (int c = 0; c < 4; c++) acc[nt][c] = 0.f;
        #pragma unroll
        for (int kst = 0; kst < 2; kst++)
            #pragma unroll
            for (int p = 0; p < 7; p++) {
                unsigned bh[4], bl[4];
                const int brow = (2*p + (lane >> 4)) * 8 + (lane & 7);
                const int bch  = kst*2 + ((lane >> 3) & 1);
                ldsm4(bh, bhi + swz(brow, bch));
                ldsm4(bl, blo + swz(brow, bch));
                #pragma unroll
                for (int t2 = 0; t2 < 2; t2++) {
                    mma16816(acc[2*p+t2], ah[kst], &bh[2*t2]);
                    mma16816(acc[2*p+t2], al[kst], &bh[2*t2]);
                    mma16816(acc[2*p+t2], ah[kst], &bl[2*t2]);
                }
            }
        #pragma unroll
        for (int nt = 0; nt < 14; nt++) {
            *(float2*)&outp[(mrow0+fr)*114   + nt*8 + fc] = make_float2(acc[nt][0], acc[nt][1]);
            *(float2*)&outp[(mrow0+fr+8)*114 + nt*8 + fc] = make_float2(acc[nt][2], acc[nt][3]);
        }
    }
    __syncthreads();

    if (wid >= 4) {
        const int mrow0 = (wid - 4) * 16;
        const float sqk = pqk[g] * rsqrtf(pqk[24+g] + EPS);
        const float sqr = pqr[g] * rsqrtf(pqr[24+g] + EPS);
        const float skr = pkr[g] * rsqrtf(pkr[24+g] + EPS);
        const float tsum = (pqk[8+g] - pqk[16+g]*sqk)
                         + (pqr[8+g] - pqr[16+g]*sqr)
                         + (pkr[8+g] - pkr[16+g]*skr);

        float qk[8][4];
        #pragma unroll
        for (int nt = 0; nt < 8; nt++)
            #pragma unroll
            for (int c = 0; c < 4; c++) qk[nt][c] = 0.f;
        unsigned ah[2][4], al[2][4];
        #pragma unroll
        for (int kst = 0; kst < 2; kst++) {
            const int row = mrow0 + (lane & 15);
            const int ch  = kst*2 + (lane >> 4);
            ldsm4(ah[kst], sb + OFF_QHI + swz(row, ch));
            ldsm4(al[kst], sb + OFF_QLO + swz(row, ch));
        }
        #pragma unroll
        for (int kst = 0; kst < 2; kst++)
            #pragma unroll
            for (int p = 0; p < 4; p++) {
                unsigned bh[4], bl[4];
                const int brow = (2*p + (lane >> 4)) * 8 + (lane & 7);
                const int bch  = kst*2 + ((lane >> 3) & 1);
                ldsm4(bh, sb + OFF_KHI + swz(brow, bch));
                ldsm4(bl, sb + OFF_KLO + swz(brow, bch));
                #pragma unroll
                for (int t2 = 0; t2 < 2; t2++) {
                    mma16816(qk[2*p+t2], ah[kst], &bh[2*t2]);
                    mma16816(qk[2*p+t2], al[kst], &bh[2*t2]);
                    mma16816(qk[2*p+t2], ah[kst], &bl[2*t2]);
                }
            }

        float* Lp = g_L + ((size_t)bw*8 + g)*3136;
        #pragma unroll
        for (int nt = 0; nt < 7; nt++) {
            const int j0 = nt*8 + fc;
            #pragma unroll
            for (int half = 0; half < 2; half++) {
                const int i = mrow0 + fr + half*8;
                if (i < 56) {
                    const int dq = 55 + i - j0;
                    float2 o;
                    o.x = sqk*qk[nt][half*2+0] + sqr*qrs[i*114 + dq]
                        + skr*krs[j0*114 + 55 + j0 - i] + tsum;
                    o.y = sqk*qk[nt][half*2+1] + sqr*qrs[i*114 + dq - 1]
                        + skr*krs[(j0+1)*114 + 56 + j0 - i] + tsum;
                    *(float2*)&Lp[i*56 + j0] = o;
                }
            }
        }
    }
}

// ---------------------------------------------------------------------------
// k3: softmax over w (axis=-2), in place
// ---------------------------------------------------------------------------
__global__ __launch_bounds__(64) void softmax_kernel()
{
    const int t  = threadIdx.x;
    const int ij = blockIdx.x * 64 + t;
    const int g  = blockIdx.y;
    const int b  = blockIdx.z;
    float* base = g_L + ((size_t)b*448 + g)*3136 + ij;
    const int ws = 8*3136;

    float v[56];
    float mx = -3.4e38f;
    #pragma unroll
    for (int w = 0; w < 56; w++) { v[w] = base[w*ws]; mx = fmaxf(mx, v[w]); }
    float s = 0.f;
    #pragma unroll
    for (int w = 0; w < 56; w++) { v[w] = __expf(v[w] - mx); s += v[w]; }
    const float inv = 1.f / s;
    #pragma unroll
    for (int w = 0; w < 56; w++) base[w*ws] = v[w] * inv;
}

// ---------------------------------------------------------------------------
// k4: attention output per (b,w,g) — SIMT; vrel read from L2 (no smem copy)
//   smem: Vg [56][64] + sim [56][56] = 26880 B -> 8 CTAs/SM
// ---------------------------------------------------------------------------
__global__ __launch_bounds__(256) void attn_out_kernel(
    const float* __restrict__ v_rel,
    const float* __restrict__ psv, const float* __restrict__ psve,
    float* __restrict__ out)
{
    extern __shared__ float smf[];
    float* Vg    = smf;              // [56][64]
    float* sim_s = smf + 3584;       // [56][56]

    const int tid = threadIdx.x;
    const int bw  = blockIdx.x;
    const int g   = blockIdx.y;
    const int b   = bw / 56, w = bw - b*56;

    const float* vsrc = g_V + (size_t)bw * (56*512) + g*64;
    for (int idx = tid; idx < 3584; idx += 256) {
        const int j = idx >> 6, c = idx & 63;
        Vg[idx] = vsrc[j*512 + c];
    }
    const float* simsrc = g_L + ((size_t)bw*8 + g)*3136;
    for (int idx = tid; idx < 3136; idx += 256) sim_s[idx] = simsrc[idx];
    __syncthreads();

    if (tid >= 224) return;
    const int ti = tid >> 4, tc = tid & 15;
    const int i0 = ti*4, c0 = tc*4;
    const int ch0 = g*64 + c0;

    float asv[4][4], asve[4][4];
    #pragma unroll
    for (int a = 0; a < 4; a++)
        #pragma unroll
        for (int c = 0; c < 4; c++) { asv[a][c]=0.f; asve[a][c]=0.f; }

    // sve term: vrel rows streamed from gmem (28KB table, L2-resident)
    for (int d = 52 - i0; d <= 110 - i0; d++) {
        const float4 vr = __ldg((const float4*)&v_rel[d*64 + c0]);
        #pragma unroll
        for (int a = 0; a < 4; a++) {
            const int j = i0 + a + d - 55;
            if ((unsigned)j < 56u) {
                const float s = sim_s[(i0+a)*56 + j];
                asve[a][0] = fmaf(s, vr.x, asve[a][0]);
                asve[a][1] = fmaf(s, vr.y, asve[a][1]);
                asve[a][2] = fmaf(s, vr.z, asve[a][2]);
                asve[a][3] = fmaf(s, vr.w, asve[a][3]);
            }
        }
    }
    // sv term: V from smem
    #pragma unroll 4
    for (int j = 0; j < 56; j++) {
        const float4 vv = *(const float4*)&Vg[j*64 + c0];
        #pragma unroll
        for (int a = 0; a < 4; a++) {
            const float s = sim_s[(i0+a)*56 + j];
            asv[a][0] = fmaf(s, vv.x, asv[a][0]);
            asv[a][1] = fmaf(s, vv.y, asv[a][1]);
            asv[a][2] = fmaf(s, vv.z, asv[a][2]);
            asv[a][3] = fmaf(s, vv.w, asv[a][3]);
        }
    }

    float s1[4], t1[4], s2[4], t2[4];
    #pragma unroll
    for (int cc = 0; cc < 4; cc++) {
        const int ch = ch0 + cc;
        const float a1 = psv[ch] * rsqrtf(psv[1536+ch] + EPS);
        s1[cc] = a1; t1[cc] = psv[512+ch] - psv[1024+ch]*a1;
        const float a2 = psve[ch] * rsqrtf(psve[1536+ch] + EPS);
        s2[cc] = a2; t2[cc] = psve[512+ch] - psve[1024+ch]*a2;
    }
    #pragma unroll
    for (int a = 0; a < 4; a++) {
        float4 o;
        o.x = asv[a][0]*s1[0] + t1[0] + asve[a][0]*s2[0] + t2[0];
        o.y = asv[a][1]*s1[1] + t1[1] + asve[a][1]*s2[1] + t2[1];
        o.z = asv[a][2]*s1[2] + t1[2] + asve[a][2]*s2[2] + t2[2];
        o.w = asv[a][3]*s1[3] + t1[3] + asve[a][3]*s2[3] + t2[3];
        *(float4*)&out[(((b*56 + i0 + a)*56 + w) * 512) + ch0] = o;
    }
}

// ---------------------------------------------------------------------------
extern "C" void kernel_launch(void* const* d_in, const int* in_sizes, int n_in,
                              void* d_out, int out_size)
{
    const float* x     = (const float*)d_in[0];
    const float* Wq    = (const float*)d_in[1];
    const float* Wk    = (const float*)d_in[2];
    const float* Wv    = (const float*)d_in[3];
    const float* q_rel = (const float*)d_in[4];
    const float* k_rel = (const float*)d_in[5];
    const float* v_rel = (const float*)d_in[6];
    const float* p_q   = (const float*)d_in[7];
    const float* p_k   = (const float*)d_in[8];
    const float* p_v   = (const float*)d_in[9];
    const float* p_qk  = (const float*)d_in[10];
    const float* p_qr  = (const float*)d_in[11];
    const float* p_kr  = (const float*)d_in[12];
    const float* p_sv  = (const float*)d_in[13];
    const float* p_sve = (const float*)d_in[14];
    float* out = (float*)d_out;

    const int smem_k4 = (3584 + 3136) * 4;  // 26880 B
    cudaFuncSetAttribute(qkv_mma_kernel,
                         cudaFuncAttributeMaxDynamicSharedMemorySize, SMEM_MMA);
    cudaFuncSetAttribute(logits_mma_kernel,
                         cudaFuncAttributeMaxDynamicSharedMemorySize, SMEM_LOGITS);
    cudaFuncSetAttribute(attn_out_kernel,
                         cudaFuncAttributeMaxDynamicSharedMemorySize, smem_k4);

    split_w_kernel<<<dim3(32, 16), 256>>>(Wq, Wk, Wv);
    qkv_mma_kernel<<<dim3(8, 392), 256, SMEM_MMA>>>(x, p_q, p_k, p_v);
    logits_mma_kernel<<<dim3(896, 8), 256, SMEM_LOGITS>>>(q_rel, k_rel, p_qk, p_qr, p_kr);
    softmax_kernel<<<dim3(49, 8, 16), 64>>>();
    attn_out_kernel<<<dim3(896, 8), 256, smem_k4>>>(v_rel, p_sv, p_sve, out);
}